// round 10
// baseline (speedup 1.0000x reference)
#include <cuda_runtime.h>

#define NLAT_I 240
#define NLON_I 480
#define NLAT_O 361
#define NLON_O 720
#define CI     32
#define CO     32
#define KK     7
#define WOFF   10

#define PI_F      3.14159265358979323846f
#define TWO_PI_F  6.28318530717958647692f
#define CUTOFF_F  0.08508480103472356f
#define DR_F      0.028361600344907855f
#define DPH_F     2.0943951023931953f

#define XSROW 784   // smem xu row length (64 + 2*360)

typedef unsigned long long u64;

// ---------------- device scratch ----------------
static __device__ float g_xu4[8 * 361 * 720 * 4];                   // [g][t][p] float4 (ch 4g..4g+3)
static __device__ float g_psi16[(size_t)361 * 21 * 728 * 16];       // [t][d][s][16] pre-dup psi
static __device__ float g_sp[7 * 361 * 21];
static __device__ float g_invsc[7 * 361];
static __device__ float g_invs2[361 * 8];
static __device__ float g_w2[32 * 112 * 2];
static __device__ int   g_m[361 * 21];
static __device__ int   g_m2[361 * 21];

// ---------------- kernel A: bilinear upsample ----------------
__global__ void upsample_kernel(const float* __restrict__ x) {
    int idx = blockIdx.x * 256 + threadIdx.x;
    if (idx >= CI * NLAT_O * NLON_O) return;
    int p  = idx % NLON_O;
    int tt = (idx / NLON_O) % NLAT_O;
    int i  = idx / (NLON_O * NLAT_O);

    float theta = (float)tt * (PI_F / 360.0f);
    float post  = theta / (PI_F / 239.0f);
    float fi0 = floorf(post);
    int i0 = (int)fi0; i0 = min(max(i0, 0), NLAT_I - 1);
    int i1 = min(i0 + 1, NLAT_I - 1);
    float wt = post - (float)i0;

    float posp = ((float)p * (TWO_PI_F / (float)NLON_O)) / (TWO_PI_F / (float)NLON_I);
    float fj0 = floorf(posp);
    int j0 = ((int)fj0) % NLON_I;
    int j1 = j0 + 1; if (j1 >= NLON_I) j1 = 0;
    float wp = posp - fj0;

    const float* xi = x + i * (NLAT_I * NLON_I);
    float a  = xi[i0 * NLON_I + j0];
    float b  = xi[i0 * NLON_I + j1];
    float c  = xi[i1 * NLON_I + j0];
    float dv = xi[i1 * NLON_I + j1];
    float xl0 = (1.0f - wt) * a + wt * c;
    float xl1 = (1.0f - wt) * b + wt * dv;
    float val = (1.0f - wp) * xl0 + wp * xl1;

    g_xu4[(((i >> 2) * NLAT_O + tt) * NLON_O + p) * 4 + (i & 3)] = val;
}

// ---------------- kernel B: build pre-dup psi + bounds ----------------
__global__ void build_psi_kernel() {
    int d = blockIdx.x;
    int t = blockIdx.y;
    int tid = threadIdx.x;

    int lt = t + d - WOFF;
    bool valid = (lt >= 0) && (lt <= NLAT_O - 1);
    int ltc = min(max(lt, 0), NLAT_O - 1);

    float tht = (float)t   * (PI_F / 360.0f);
    float thi = (float)ltc * (PI_F / 360.0f);
    float ca = cosf(tht), sa = sinf(tht);
    float cg = cosf(thi), sg = sinf(thi);
    float A = ca * cg;
    float B = sa * sg;
    float cosc = cosf(CUTOFF_F);

    int m;
    if (!valid)                 m = -1;
    else if (A - B >= cosc)     m = 360;
    else if (A + B <  cosc)     m = -1;
    else {
        float ratio = (cosc - A) / fmaxf(B, 1e-30f);
        ratio = fminf(fmaxf(ratio, -1.0f), 1.0f);
        m = (int)floorf(acosf(ratio) * (360.0f / PI_F)) + 2;
        if (m > 360) m = 360;
    }

    float cosc2i = cosf(2.0f * DR_F);
    float cosc2o = cosf(2.0f * DR_F + 1e-4f);
    int m2;
    if (m < 0)                   m2 = -1;
    else if (A - B >= cosc2i)    m2 = 360;
    else if (A + B <  cosc2o)    m2 = -1;
    else {
        float ratio = (cosc2o - A) / fmaxf(B, 1e-30f);
        ratio = fminf(fmaxf(ratio, -1.0f), 1.0f);
        m2 = (int)floorf(acosf(ratio) * (360.0f / PI_F)) + 3;
        if (m2 > 360) m2 = 360;
    }
    if (tid == 0) { g_m[t * 21 + d] = m; g_m2[t * 21 + d] = m2; }

    float dth = (float)(ltc - t) * (PI_F / 360.0f);
    float shd = sinf(0.5f * dth);
    float hav_lat = shd * shd;

    float sums[7] = {0.f, 0.f, 0.f, 0.f, 0.f, 0.f, 0.f};
    if (m >= 0) {
        float qfac = sg * (PI_F / 360.0f) * (PI_F / 360.0f);
        int cnt = 2 * m + 1;
        for (int s = tid; s < cnt; s += 256) {
            int pp = s - m; if (pp < 0) pp += NLON_O;
            float beta = (float)pp * (TWO_PI_F / (float)NLON_O);
            float cb = cosf(beta), sb = sinf(beta);
            float z = A + cb * B;
            z = fminf(fmaxf(z, -1.0f), 1.0f);
            float r_acos = acosf(z);
            float mask = (r_acos <= CUTOFF_F) ? qfac : 0.0f;
            float sbh = sinf(0.5f * beta);
            float h = hav_lat + B * sbh * sbh;
            float r = 2.0f * asinf(fminf(sqrtf(fmaxf(h, 0.0f)), 1.0f));

            float xx = ca * cb * sg - sa * cg;
            float yy = sb * sg;
            float phi = atan2f(yy, xx);
            if (phi < 0.0f) phi += TWO_PI_F;

            float v[7];
            v[0] = fmaxf(0.0f, 1.0f - r * (1.0f / DR_F)) * mask;
            #pragma unroll
            for (int k = 1; k < 7; ++k) {
                int ir = (k - 1) / 3 + 1;
                int ip = (k - 1) % 3;
                float rad = fmaxf(0.0f, 1.0f - fabsf(r - (float)ir * DR_F) * (1.0f / DR_F));
                float dd  = fabsf(phi - (float)ip * DPH_F);
                dd = fminf(dd, TWO_PI_F - dd);
                float az = fmaxf(0.0f, 1.0f - dd * (1.0f / DPH_F));
                v[k] = rad * az * mask;
            }
            size_t b16 = ((size_t)(t * 21 + d) * 728 + s) * 16;
            g_psi16[b16 + 0] = v[0];
            g_psi16[b16 + 1] = v[1];
            g_psi16[b16 + 2] = v[2];
            g_psi16[b16 + 3] = v[3];
            g_psi16[b16 + 4] = v[4];
            g_psi16[b16 + 5] = v[4];
            g_psi16[b16 + 6] = v[5];
            g_psi16[b16 + 7] = v[5];
            g_psi16[b16 + 8] = v[6];
            g_psi16[b16 + 9] = v[6];
            #pragma unroll
            for (int k = 0; k < 7; ++k) sums[k] += v[k];
        }
    }

    __shared__ float red[8][7];
    int lane = tid & 31, w = tid >> 5;
    #pragma unroll
    for (int k = 0; k < 7; ++k) {
        float s = sums[k];
        #pragma unroll
        for (int o = 16; o > 0; o >>= 1) s += __shfl_down_sync(0xffffffffu, s, o);
        if (lane == 0) red[w][k] = s;
    }
    __syncthreads();
    if (tid < 7) {
        float s = 0.0f;
        #pragma unroll
        for (int ww = 0; ww < 8; ++ww) s += red[ww][tid];
        g_sp[(tid * 361 + t) * 21 + d] = s;
    }
}

// ---------------- kernel INV ----------------
__global__ void inv_kernel() {
    int i = blockIdx.x * blockDim.x + threadIdx.x;
    if (i < 7 * 361) {
        float s = 0.0f;
        #pragma unroll
        for (int d = 0; d < 21; ++d) s += g_sp[i * 21 + d];
        g_invsc[i] = 1.0f / fmaxf(s, 1e-8f);
    }
}

// ---------------- kernel PACK ----------------
__global__ void pack_kernel(const float* __restrict__ wgt) {
    int idx = blockIdx.x * 256 + threadIdx.x;
    if (idx < 32 * 112) {
        int o = idx / 112;
        int j = idx - o * 112;
        int k = j >> 4;
        int h = j & 15;
        g_w2[idx * 2 + 0] = wgt[(o * CI + 2 * h) * KK + k];
        g_w2[idx * 2 + 1] = wgt[(o * CI + 2 * h + 1) * KK + k];
    }
    if (idx < 361) {
        #pragma unroll
        for (int k = 0; k < 7; ++k) g_invs2[idx * 8 + k] = g_invsc[k * 361 + idx];
        g_invs2[idx * 8 + 7] = 0.0f;
    }
}

// ---------------- kernel C: conv (smem xu + uniform-LDG psi prefetch) + GEMM ----------------
// phase1 smem: xu float4[8][784] = 100352B ; phase2 (aliased): z2 = 57344B
#define SMEM_C (8 * XSROW * 16)

#define PDUP(dst, v)     asm("mov.b64 %0,{%1,%1};" : "=l"(dst) : "f"(v))
#define CPAIR(dst, a, b) asm("mov.b64 %0,{%1,%2};" : "=l"(dst) : "f"(a), "f"(b))
#define UNP(lo, hi, v)   asm("mov.b64 {%0,%1},%2;" : "=f"(lo), "=f"(hi) : "l"(v))
#define F2(acc, p, x)    asm("fma.rn.f32x2 %0,%1,%2,%0;" : "+l"(acc) : "l"(p), "l"(x))
#define M2(acc, s)       asm("mul.rn.f32x2 %0,%0,%1;" : "+l"(acc) : "l"(s))

#define LOADP(P, S)                                                          \
    asm("ld.global.nc.v2.u64 {%0,%1},[%2];" : "=l"(P##01), "=l"(P##23)       \
        : "l"(pb + (size_t)(S) * 64));                                       \
    asm("ld.global.nc.v2.u64 {%0,%1},[%2];" : "=l"(P##44), "=l"(P##55)       \
        : "l"(pb + (size_t)(S) * 64 + 16));                                  \
    asm("ld.global.nc.u64 %0,[%1];" : "=l"(P##66)                            \
        : "l"(pb + (size_t)(S) * 64 + 32));

#define BODY(S, P) {                                                         \
    float4 x0 = xq0[S];                                                      \
    float4 x1 = xq1[S];                                                      \
    u64 c01, c23, c45, c67;                                                  \
    CPAIR(c01, x0.x, x0.y); CPAIR(c23, x0.z, x0.w);                          \
    CPAIR(c45, x1.x, x1.y); CPAIR(c67, x1.z, x1.w);                          \
    F2(aK4[0], P##44, c01); F2(aK4[1], P##44, c23);                          \
    F2(aK4[2], P##44, c45); F2(aK4[3], P##44, c67);                          \
    F2(aK5[0], P##55, c01); F2(aK5[1], P##55, c23);                          \
    F2(aK5[2], P##55, c45); F2(aK5[3], P##55, c67);                          \
    F2(aK6[0], P##66, c01); F2(aK6[1], P##66, c23);                          \
    F2(aK6[2], P##66, c45); F2(aK6[3], P##66, c67);                          \
    if ((unsigned)((S) - iA) < inlen) {                                      \
        u64 du;                                                              \
        PDUP(du, x0.x); F2(a01[0], P##01, du); F2(a23[0], P##23, du);        \
        PDUP(du, x0.y); F2(a01[1], P##01, du); F2(a23[1], P##23, du);        \
        PDUP(du, x0.z); F2(a01[2], P##01, du); F2(a23[2], P##23, du);        \
        PDUP(du, x0.w); F2(a01[3], P##01, du); F2(a23[3], P##23, du);        \
        PDUP(du, x1.x); F2(a01[4], P##01, du); F2(a23[4], P##23, du);        \
        PDUP(du, x1.y); F2(a01[5], P##01, du); F2(a23[5], P##23, du);        \
        PDUP(du, x1.z); F2(a01[6], P##01, du); F2(a23[6], P##23, du);        \
        PDUP(du, x1.w); F2(a01[7], P##01, du); F2(a23[7], P##23, du);        \
    } }

__global__ void __launch_bounds__(256, 2)
conv_kernel(float* __restrict__ y) {
    extern __shared__ float sm[];
    float4* xu_s = (float4*)sm;                         // [8][784]

    int ty = blockIdx.y;
    int t  = (ty & 1) ? (360 - (ty >> 1)) : (ty >> 1);  // heavy rows first
    int p0 = blockIdx.x * 64;
    int tid  = threadIdx.x;
    int lane = tid & 31;
    int wpi  = tid >> 5;
    int sub  = wpi & 1;
    int cg   = wpi >> 1;
    int qb   = 32 * sub + lane;

    u64 a01[8], a23[8], aK4[4], aK5[4], aK6[4];
    #pragma unroll
    for (int c = 0; c < 8; ++c) { a01[c] = 0ull; a23[c] = 0ull; }
    #pragma unroll
    for (int j = 0; j < 4; ++j) { aK4[j] = 0ull; aK5[j] = 0ull; aK6[j] = 0ull; }

    const float4* gx = (const float4*)g_xu4;

    for (int d = 0; d < 21; ++d) {
        int lt = t + d - WOFF;
        if (lt < 0 || lt > 360) continue;
        int m = g_m[t * 21 + d];
        if (m < 0) continue;
        int m2 = g_m2[t * 21 + d];
        int cnt = 2 * m + 1;
        int L = 64 + 2 * m;                 // <= 784
        int base = p0 - m;
        base %= 720; if (base < 0) base += 720;
        int iA;
        unsigned inlen;
        if (m2 < 0) { iA = 0; inlen = 0u; }
        else {
            iA = max(0, m - m2);
            int iB = min(cnt, m + m2 + 1);
            inlen = (unsigned)(iB - iA);
        }

        __syncthreads();
        // stage xu window (wrap folded here): warp wpi stages group wpi
        {
            const float4* src = gx + ((size_t)wpi * NLAT_O + lt) * NLON_O;
            for (int q = lane; q < L; q += 32) {
                int lon = base + q;
                if (lon >= 720) lon -= 720;
                if (lon >= 720) lon -= 720;
                xu_s[wpi * XSROW + q] = src[lon];
            }
        }
        __syncthreads();

        const float4* xq0 = xu_s + (2 * cg) * XSROW + qb;
        const float4* xq1 = xq0 + XSROW;
        const char* pb = (const char*)g_psi16 + (size_t)(t * 21 + d) * (728 * 64);

        u64 A01, A23, A44, A55, A66;
        u64 B01, B23, B44, B55, B66;
        LOADP(A, 0)
        LOADP(B, 1)
        int s = 0;
        for (; s + 1 < cnt; s += 2) {
            BODY(s, A)
            LOADP(A, s + 2)
            BODY(s + 1, B)
            LOADP(B, s + 3)
        }
        if (s < cnt) BODY(s, A)
    }

    // ---- fold 1/scale ----
    {
        const float* iv = g_invs2 + t * 8;
        u64 i01 = *(const u64*)(iv);
        u64 i23 = *(const u64*)(iv + 2);
        u64 d4, d5, d6;
        PDUP(d4, iv[4]); PDUP(d5, iv[5]); PDUP(d6, iv[6]);
        #pragma unroll
        for (int c = 0; c < 8; ++c) { M2(a01[c], i01); M2(a23[c], i23); }
        #pragma unroll
        for (int j = 0; j < 4; ++j) { M2(aK4[j], d4); M2(aK5[j], d5); M2(aK6[j], d6); }
    }

    __syncthreads();
    // ---- phase 2: scatter z [112 kpair][64 p][2 par], GEMM ----
    float* z2f = sm;
    u64*   z2w = (u64*)sm;
    {
        #pragma unroll
        for (int c = 0; c < 8; ++c) {
            int i = 8 * cg + c;
            int half = i >> 1, par = i & 1;
            float lo, hi;
            UNP(lo, hi, a01[c]);
            z2f[(((0 * 16 + half) * 64 + qb) * 2) + par] = lo;
            z2f[(((1 * 16 + half) * 64 + qb) * 2) + par] = hi;
            UNP(lo, hi, a23[c]);
            z2f[(((2 * 16 + half) * 64 + qb) * 2) + par] = lo;
            z2f[(((3 * 16 + half) * 64 + qb) * 2) + par] = hi;
        }
        #pragma unroll
        for (int j = 0; j < 4; ++j) {
            int half = 4 * cg + j;
            z2w[(4 * 16 + half) * 64 + qb] = aK4[j];
            z2w[(5 * 16 + half) * 64 + qb] = aK5[j];
            z2w[(6 * 16 + half) * 64 + qb] = aK6[j];
        }
    }
    __syncthreads();

    int po2 = tid & 31;
    int og  = (tid >> 5) & 7;
    const ulonglong2* zp = (const ulonglong2*)z2f;
    const u64* wu = (const u64*)g_w2;

    u64 acc0[4], acc1[4];
    #pragma unroll
    for (int oo = 0; oo < 4; ++oo) { acc0[oo] = 0ull; acc1[oo] = 0ull; }

    for (int j = 0; j < 112; ++j) {
        ulonglong2 zv = zp[j * 32 + po2];
        #pragma unroll
        for (int oo = 0; oo < 4; ++oo) {
            u64 wv = __ldg(wu + (og + 8 * oo) * 112 + j);
            F2(acc0[oo], wv, zv.x);
            F2(acc1[oo], wv, zv.y);
        }
    }

    int pA0 = p0 + 2 * po2;
    int pA1 = pA0 + 1;
    #pragma unroll
    for (int oo = 0; oo < 4; ++oo) {
        int o = og + 8 * oo;
        float lo, hi;
        if (pA0 < 720) {
            UNP(lo, hi, acc0[oo]);
            y[((size_t)o * NLAT_O + t) * NLON_O + pA0] = lo + hi;
        }
        if (pA1 < 720) {
            UNP(lo, hi, acc1[oo]);
            y[((size_t)o * NLAT_O + t) * NLON_O + pA1] = lo + hi;
        }
    }
}

// ---------------- launcher ----------------
extern "C" void kernel_launch(void* const* d_in, const int* in_sizes, int n_in,
                              void* d_out, int out_size) {
    const float* x = (const float*)d_in[0];       // [1,32,240,480]
    const float* w = (const float*)d_in[1];       // [32,32,7]
    float* y = (float*)d_out;                     // [1,32,361,720]

    cudaFuncSetAttribute(conv_kernel, cudaFuncAttributeMaxDynamicSharedMemorySize, SMEM_C);

    int nA = CI * NLAT_O * NLON_O;
    upsample_kernel<<<(nA + 255) / 256, 256>>>(x);
    build_psi_kernel<<<dim3(21, 361), 256>>>();
    inv_kernel<<<(7 * 361 + 255) / 256, 256>>>();
    pack_kernel<<<(32 * 112 + 255) / 256, 256>>>(w);
    conv_kernel<<<dim3(12, 361), 256, SMEM_C>>>(y);
}

// round 11
// speedup vs baseline: 1.6070x; 1.6070x over previous
#include <cuda_runtime.h>

#define NLAT_I 240
#define NLON_I 480
#define NLAT_O 361
#define NLON_O 720
#define CI     32
#define CO     32
#define KK     7
#define WOFF   10

#define PI_F      3.14159265358979323846f
#define TWO_PI_F  6.28318530717958647692f
#define CUTOFF_F  0.08508480103472356f
#define DR_F      0.028361600344907855f
#define DPH_F     2.0943951023931953f

typedef unsigned long long u64;

// ---------------- device scratch ----------------
static __device__ float g_xu4[8 * 361 * 720 * 4];                  // [g][t][p] float4 (ch 4g..4g+3)
static __device__ float g_psi8[(size_t)361 * 21 * 728 * 8];        // [t][d][s][8] = k0..k6, pad
static __device__ float g_sp[7 * 361 * 21];
static __device__ float g_invsc[7 * 361];
static __device__ float g_invs2[361 * 8];                          // (i0..i6,0) per t
static __device__ float g_w2[32 * 112 * 2];                        // packed weight pairs
static __device__ int   g_m[361 * 21];
static __device__ int   g_m2[361 * 21];

// ---------------- kernel A: bilinear upsample ----------------
__global__ void upsample_kernel(const float* __restrict__ x) {
    int idx = blockIdx.x * 256 + threadIdx.x;
    if (idx >= CI * NLAT_O * NLON_O) return;
    int p  = idx % NLON_O;
    int tt = (idx / NLON_O) % NLAT_O;
    int i  = idx / (NLON_O * NLAT_O);

    float theta = (float)tt * (PI_F / 360.0f);
    float post  = theta / (PI_F / 239.0f);
    float fi0 = floorf(post);
    int i0 = (int)fi0; i0 = min(max(i0, 0), NLAT_I - 1);
    int i1 = min(i0 + 1, NLAT_I - 1);
    float wt = post - (float)i0;

    float posp = ((float)p * (TWO_PI_F / (float)NLON_O)) / (TWO_PI_F / (float)NLON_I);
    float fj0 = floorf(posp);
    int j0 = ((int)fj0) % NLON_I;
    int j1 = j0 + 1; if (j1 >= NLON_I) j1 = 0;
    float wp = posp - fj0;

    const float* xi = x + i * (NLAT_I * NLON_I);
    float a  = xi[i0 * NLON_I + j0];
    float b  = xi[i0 * NLON_I + j1];
    float c  = xi[i1 * NLON_I + j0];
    float dv = xi[i1 * NLON_I + j1];
    float xl0 = (1.0f - wt) * a + wt * c;
    float xl1 = (1.0f - wt) * b + wt * dv;
    float val = (1.0f - wp) * xl0 + wp * xl1;

    g_xu4[(((i >> 2) * NLAT_O + tt) * NLON_O + p) * 4 + (i & 3)] = val;
}

// ---------------- kernel B: build psi (slots k0..k6) + bounds ----------------
__global__ void build_psi_kernel() {
    int d = blockIdx.x;
    int t = blockIdx.y;
    int tid = threadIdx.x;

    int lt = t + d - WOFF;
    bool valid = (lt >= 0) && (lt <= NLAT_O - 1);
    int ltc = min(max(lt, 0), NLAT_O - 1);

    float tht = (float)t   * (PI_F / 360.0f);
    float thi = (float)ltc * (PI_F / 360.0f);
    float ca = cosf(tht), sa = sinf(tht);
    float cg = cosf(thi), sg = sinf(thi);
    float A = ca * cg;
    float B = sa * sg;
    float cosc = cosf(CUTOFF_F);

    int m;
    if (!valid)                 m = -1;
    else if (A - B >= cosc)     m = 360;
    else if (A + B <  cosc)     m = -1;
    else {
        float ratio = (cosc - A) / fmaxf(B, 1e-30f);
        ratio = fminf(fmaxf(ratio, -1.0f), 1.0f);
        m = (int)floorf(acosf(ratio) * (360.0f / PI_F)) + 2;
        if (m > 360) m = 360;
    }

    float cosc2i = cosf(2.0f * DR_F);
    float cosc2o = cosf(2.0f * DR_F + 1e-4f);
    int m2;
    if (m < 0)                   m2 = -1;
    else if (A - B >= cosc2i)    m2 = 360;
    else if (A + B <  cosc2o)    m2 = -1;
    else {
        float ratio = (cosc2o - A) / fmaxf(B, 1e-30f);
        ratio = fminf(fmaxf(ratio, -1.0f), 1.0f);
        m2 = (int)floorf(acosf(ratio) * (360.0f / PI_F)) + 3;
        if (m2 > 360) m2 = 360;
    }
    if (tid == 0) { g_m[t * 21 + d] = m; g_m2[t * 21 + d] = m2; }

    float dth = (float)(ltc - t) * (PI_F / 360.0f);
    float shd = sinf(0.5f * dth);
    float hav_lat = shd * shd;

    float sums[7] = {0.f, 0.f, 0.f, 0.f, 0.f, 0.f, 0.f};
    if (m >= 0) {
        float qfac = sg * (PI_F / 360.0f) * (PI_F / 360.0f);
        int cnt = 2 * m + 1;
        for (int s = tid; s < cnt; s += 256) {
            int pp = s - m; if (pp < 0) pp += NLON_O;
            float beta = (float)pp * (TWO_PI_F / (float)NLON_O);
            float cb = cosf(beta), sb = sinf(beta);
            float z = A + cb * B;
            z = fminf(fmaxf(z, -1.0f), 1.0f);
            float r_acos = acosf(z);
            float mask = (r_acos <= CUTOFF_F) ? qfac : 0.0f;
            float sbh = sinf(0.5f * beta);
            float h = hav_lat + B * sbh * sbh;
            float r = 2.0f * asinf(fminf(sqrtf(fmaxf(h, 0.0f)), 1.0f));

            float xx = ca * cb * sg - sa * cg;
            float yy = sb * sg;
            float phi = atan2f(yy, xx);
            if (phi < 0.0f) phi += TWO_PI_F;

            float v[7];
            v[0] = fmaxf(0.0f, 1.0f - r * (1.0f / DR_F)) * mask;
            #pragma unroll
            for (int k = 1; k < 7; ++k) {
                int ir = (k - 1) / 3 + 1;
                int ip = (k - 1) % 3;
                float rad = fmaxf(0.0f, 1.0f - fabsf(r - (float)ir * DR_F) * (1.0f / DR_F));
                float dd  = fabsf(phi - (float)ip * DPH_F);
                dd = fminf(dd, TWO_PI_F - dd);
                float az = fmaxf(0.0f, 1.0f - dd * (1.0f / DPH_F));
                v[k] = rad * az * mask;
            }
            size_t b8 = ((size_t)(t * 21 + d) * 728 + s) * 8;
            #pragma unroll
            for (int k = 0; k < 7; ++k) g_psi8[b8 + k] = v[k];
            g_psi8[b8 + 7] = 0.0f;
            #pragma unroll
            for (int k = 0; k < 7; ++k) sums[k] += v[k];
        }
    }

    __shared__ float red[8][7];
    int lane = tid & 31, w = tid >> 5;
    #pragma unroll
    for (int k = 0; k < 7; ++k) {
        float s = sums[k];
        #pragma unroll
        for (int o = 16; o > 0; o >>= 1) s += __shfl_down_sync(0xffffffffu, s, o);
        if (lane == 0) red[w][k] = s;
    }
    __syncthreads();
    if (tid < 7) {
        float s = 0.0f;
        #pragma unroll
        for (int ww = 0; ww < 8; ++ww) s += red[ww][tid];
        g_sp[(tid * 361 + t) * 21 + d] = s;
    }
}

// ---------------- kernel INV ----------------
__global__ void inv_kernel() {
    int i = blockIdx.x * blockDim.x + threadIdx.x;
    if (i < 7 * 361) {
        float s = 0.0f;
        #pragma unroll
        for (int d = 0; d < 21; ++d) s += g_sp[i * 21 + d];
        g_invsc[i] = 1.0f / fmaxf(s, 1e-8f);
    }
}

// ---------------- kernel PACK ----------------
__global__ void pack_kernel(const float* __restrict__ wgt) {
    int idx = blockIdx.x * 256 + threadIdx.x;
    if (idx < 32 * 112) {
        int o = idx / 112;
        int j = idx - o * 112;
        int k = j >> 4;
        int h = j & 15;
        g_w2[idx * 2 + 0] = wgt[(o * CI + 2 * h) * KK + k];
        g_w2[idx * 2 + 1] = wgt[(o * CI + 2 * h + 1) * KK + k];
    }
    if (idx < 361) {
        #pragma unroll
        for (int k = 0; k < 7; ++k) g_invs2[idx * 8 + k] = g_invsc[k * 361 + idx];
        g_invs2[idx * 8 + 7] = 0.0f;
    }
}

// ---------------- kernel C: conv + fused GEMM ----------------
// phase1 smem: xu float4[8][720] (92160B) + psi float[728][8] (23296B) = 115456B
// phase2 (aliased): z2 float[112][64][2] = 57344B
#define SMEM_C (8 * 720 * 16 + 728 * 8 * 4)

#define PDUP(dst, v)     asm("mov.b64 %0,{%1,%1};" : "=l"(dst) : "f"(v))
#define CPAIR(dst, a, b) asm("mov.b64 %0,{%1,%2};" : "=l"(dst) : "f"(a), "f"(b))
#define UNP(lo, hi, v)   asm("mov.b64 {%0,%1},%2;" : "=f"(lo), "=f"(hi) : "l"(v))
#define F2(acc, p, x)    asm("fma.rn.f32x2 %0,%1,%2,%0;" : "+l"(acc) : "l"(p), "l"(x))
#define M2(acc, s)       asm("mul.rn.f32x2 %0,%0,%1;" : "+l"(acc) : "l"(s))

// shell (k4,k5,k6): 3 scalar smem broadcasts, channel-paired FMAs
#define SHELL(SS)                                                        \
    float k4s, k5s, k6s;                                                 \
    asm("ld.shared.v2.f32 {%0,%1},[%2];" : "=f"(k4s), "=f"(k5s)          \
        : "r"(psi_u + (unsigned)(SS) * 32u + 16u));                      \
    asm("ld.shared.f32 %0,[%1];" : "=f"(k6s)                             \
        : "r"(psi_u + (unsigned)(SS) * 32u + 24u));                      \
    u64 pk4, pk5, pk6;                                                   \
    PDUP(pk4, k4s); PDUP(pk5, k5s); PDUP(pk6, k6s);                      \
    F2(aK4[0], pk4, c01); F2(aK4[1], pk4, c23);                          \
    F2(aK4[2], pk4, c45); F2(aK4[3], pk4, c67);                          \
    F2(aK5[0], pk5, c01); F2(aK5[1], pk5, c23);                          \
    F2(aK5[2], pk5, c45); F2(aK5[3], pk5, c67);                          \
    F2(aK6[0], pk6, c01); F2(aK6[1], pk6, c23);                          \
    F2(aK6[2], pk6, c45); F2(aK6[3], pk6, c67);

#define BODY_OUT(Q, SS) {                                                \
    float4 x0 = xr0[Q];                                                  \
    float4 x1 = xr1[Q];                                                  \
    u64 c01, c23, c45, c67;                                              \
    CPAIR(c01, x0.x, x0.y); CPAIR(c23, x0.z, x0.w);                      \
    CPAIR(c45, x1.x, x1.y); CPAIR(c67, x1.z, x1.w);                      \
    SHELL(SS) }

#define BODY_IN(Q, SS) {                                                 \
    float4 x0 = xr0[Q];                                                  \
    float4 x1 = xr1[Q];                                                  \
    u64 c01, c23, c45, c67;                                              \
    CPAIR(c01, x0.x, x0.y); CPAIR(c23, x0.z, x0.w);                      \
    CPAIR(c45, x1.x, x1.y); CPAIR(c67, x1.z, x1.w);                      \
    u64 p01, p23;                                                        \
    asm("ld.shared.v2.u64 {%0,%1},[%2];" : "=l"(p01), "=l"(p23)          \
        : "r"(psi_u + (unsigned)(SS) * 32u));                            \
    u64 du;                                                              \
    PDUP(du, x0.x); F2(a01[0], p01, du); F2(a23[0], p23, du);            \
    PDUP(du, x0.y); F2(a01[1], p01, du); F2(a23[1], p23, du);            \
    PDUP(du, x0.z); F2(a01[2], p01, du); F2(a23[2], p23, du);            \
    PDUP(du, x0.w); F2(a01[3], p01, du); F2(a23[3], p23, du);            \
    PDUP(du, x1.x); F2(a01[4], p01, du); F2(a23[4], p23, du);            \
    PDUP(du, x1.y); F2(a01[5], p01, du); F2(a23[5], p23, du);            \
    PDUP(du, x1.z); F2(a01[6], p01, du); F2(a23[6], p23, du);            \
    PDUP(du, x1.w); F2(a01[7], p01, du); F2(a23[7], p23, du);            \
    SHELL(SS) }

__global__ void __launch_bounds__(256, 2)
conv_kernel(float* __restrict__ y) {
    extern __shared__ float sm[];
    float4* xu_s  = (float4*)sm;                        // [8][720]
    float*  psi_s = sm + 8 * 720 * 4;                   // [728][8]
    unsigned psi_u = (unsigned)__cvta_generic_to_shared(psi_s);

    int ty = blockIdx.y;
    int t  = (ty & 1) ? (360 - (ty >> 1)) : (ty >> 1);  // heavy rows first
    int p0 = blockIdx.x * 64;
    int tid  = threadIdx.x;
    int lane = tid & 31;
    int wpi  = tid >> 5;
    int sub  = wpi & 1;                                 // p-subtile
    int cg   = wpi >> 1;                                // channel octet
    int qb   = 32 * sub + lane;

    u64 a01[8], a23[8], aK4[4], aK5[4], aK6[4];
    #pragma unroll
    for (int c = 0; c < 8; ++c) { a01[c] = 0ull; a23[c] = 0ull; }
    #pragma unroll
    for (int j = 0; j < 4; ++j) { aK4[j] = 0ull; aK5[j] = 0ull; aK6[j] = 0ull; }

    const float4* gx = (const float4*)g_xu4;

    for (int d = 0; d < 21; ++d) {
        int lt = t + d - WOFF;
        if (lt < 0 || lt > 360) continue;
        int m = g_m[t * 21 + d];
        if (m < 0) continue;
        int m2 = g_m2[t * 21 + d];
        int cnt = 2 * m + 1;
        int L = 64 + 2 * m;
        int n = (L < 720) ? L : 720;
        int base = p0 - m;
        base %= 720; if (base < 0) base += 720;
        int iA, iB;
        if (m2 < 0) { iA = cnt; iB = cnt; }
        else { iA = max(0, m - m2); iB = min(cnt, m + m2 + 1); }

        __syncthreads();
        // stage xu window: warp wpi stages group wpi
        {
            const float4* src = gx + ((size_t)wpi * NLAT_O + lt) * NLON_O;
            for (int q = lane; q < n; q += 32) {
                int lon = base + q; if (lon >= 720) lon -= 720;
                xu_s[wpi * 720 + q] = src[lon];
            }
        }
        // stage psi (pure copy, 32B per s-entry)
        {
            const float4* src = (const float4*)(g_psi8 + ((size_t)(t * 21 + d)) * 728 * 8);
            float4* dst = (float4*)psi_s;
            for (int s2 = tid; s2 < 2 * cnt; s2 += 256) dst[s2] = src[s2];
        }
        __syncthreads();

        int s = 0;
        if (n < 720) {
            const float4* xr0 = xu_s + (2 * cg) * 720 + qb;   // qb+s <= 63+2m = n-1
            const float4* xr1 = xr0 + 720;
            for (; s < iA; ++s) BODY_OUT(s, s)
            for (; s < iB; ++s) BODY_IN(s, s)
            for (; s < cnt; ++s) BODY_OUT(s, s)
        } else {
            const float4* xr0 = xu_s + (2 * cg) * 720;
            const float4* xr1 = xr0 + 720;
            int q = qb;
            for (; s < iA; ++s) { BODY_OUT(q, s) ++q; if (q >= 720) q -= 720; }
            for (; s < iB; ++s) { BODY_IN(q, s) ++q; if (q >= 720) q -= 720; }
            for (; s < cnt; ++s) { BODY_OUT(q, s) ++q; if (q >= 720) q -= 720; }
        }
    }

    // ---- fold 1/scale ----
    {
        const float* iv = g_invs2 + t * 8;
        u64 i01 = *(const u64*)(iv);
        u64 i23 = *(const u64*)(iv + 2);
        u64 d4, d5, d6;
        PDUP(d4, iv[4]); PDUP(d5, iv[5]); PDUP(d6, iv[6]);
        #pragma unroll
        for (int c = 0; c < 8; ++c) { M2(a01[c], i01); M2(a23[c], i23); }
        #pragma unroll
        for (int j = 0; j < 4; ++j) { M2(aK4[j], d4); M2(aK5[j], d5); M2(aK6[j], d6); }
    }

    __syncthreads();
    // ---- phase 2: scatter z [112 kpair][64 p][2 par], GEMM ----
    float* z2f = sm;
    u64*   z2w = (u64*)sm;
    {
        #pragma unroll
        for (int c = 0; c < 8; ++c) {
            int i = 8 * cg + c;
            int half = i >> 1, par = i & 1;
            float lo, hi;
            UNP(lo, hi, a01[c]);
            z2f[(((0 * 16 + half) * 64 + qb) * 2) + par] = lo;
            z2f[(((1 * 16 + half) * 64 + qb) * 2) + par] = hi;
            UNP(lo, hi, a23[c]);
            z2f[(((2 * 16 + half) * 64 + qb) * 2) + par] = lo;
            z2f[(((3 * 16 + half) * 64 + qb) * 2) + par] = hi;
        }
        #pragma unroll
        for (int j = 0; j < 4; ++j) {
            int half = 4 * cg + j;
            z2w[(4 * 16 + half) * 64 + qb] = aK4[j];
            z2w[(5 * 16 + half) * 64 + qb] = aK5[j];
            z2w[(6 * 16 + half) * 64 + qb] = aK6[j];
        }
    }
    __syncthreads();

    // GEMM: thread = 2 adjacent p x 4 o
    int po2 = tid & 31;
    int og  = (tid >> 5) & 7;
    const ulonglong2* zp = (const ulonglong2*)z2f;
    const u64* wu = (const u64*)g_w2;

    u64 acc0[4], acc1[4];
    #pragma unroll
    for (int oo = 0; oo < 4; ++oo) { acc0[oo] = 0ull; acc1[oo] = 0ull; }

    for (int j = 0; j < 112; ++j) {
        ulonglong2 zv = zp[j * 32 + po2];
        #pragma unroll
        for (int oo = 0; oo < 4; ++oo) {
            u64 wv = __ldg(wu + (og + 8 * oo) * 112 + j);
            F2(acc0[oo], wv, zv.x);
            F2(acc1[oo], wv, zv.y);
        }
    }

    int pA0 = p0 + 2 * po2;
    int pA1 = pA0 + 1;
    #pragma unroll
    for (int oo = 0; oo < 4; ++oo) {
        int o = og + 8 * oo;
        float lo, hi;
        if (pA0 < 720) {
            UNP(lo, hi, acc0[oo]);
            y[((size_t)o * NLAT_O + t) * NLON_O + pA0] = lo + hi;
        }
        if (pA1 < 720) {
            UNP(lo, hi, acc1[oo]);
            y[((size_t)o * NLAT_O + t) * NLON_O + pA1] = lo + hi;
        }
    }
}

// ---------------- launcher ----------------
extern "C" void kernel_launch(void* const* d_in, const int* in_sizes, int n_in,
                              void* d_out, int out_size) {
    const float* x = (const float*)d_in[0];       // [1,32,240,480]
    const float* w = (const float*)d_in[1];       // [32,32,7]
    float* y = (float*)d_out;                     // [1,32,361,720]

    cudaFuncSetAttribute(conv_kernel, cudaFuncAttributeMaxDynamicSharedMemorySize, SMEM_C);

    int nA = CI * NLAT_O * NLON_O;
    upsample_kernel<<<(nA + 255) / 256, 256>>>(x);
    build_psi_kernel<<<dim3(21, 361), 256>>>();
    inv_kernel<<<(7 * 361 + 255) / 256, 256>>>();
    pack_kernel<<<(32 * 112 + 255) / 256, 256>>>(w);
    conv_kernel<<<dim3(12, 361), 256, SMEM_C>>>(y);
}

// round 12
// speedup vs baseline: 1.6173x; 1.0064x over previous
#include <cuda_runtime.h>

#define NLAT_I 240
#define NLON_I 480
#define NLAT_O 361
#define NLON_O 720
#define CI     32
#define CO     32
#define KK     7
#define WOFF   10

#define PI_F      3.14159265358979323846f
#define TWO_PI_F  6.28318530717958647692f
#define CUTOFF_F  0.08508480103472356f
#define DR_F      0.028361600344907855f
#define DPH_F     2.0943951023931953f

typedef unsigned long long u64;

// ---------------- device scratch ----------------
static __device__ float g_xu4[8 * 361 * 720 * 4];                  // [g][t][p] float4 (ch 4g..4g+3)
static __device__ float g_psi8[(size_t)361 * 21 * 728 * 8];        // [t][d][s][8] = k0..k6, pad
static __device__ float g_sp[7 * 361 * 21];
static __device__ float g_invsc[7 * 361];
static __device__ float g_invs2[361 * 8];                          // (i0..i6,0) per t
static __device__ float g_w2[32 * 112 * 2];                        // packed weight pairs
static __device__ int   g_m[361 * 21];
static __device__ int   g_m2[361 * 21];
static __device__ int   g_m1[361 * 21];

// ---------------- kernel A: bilinear upsample ----------------
__global__ void upsample_kernel(const float* __restrict__ x) {
    int idx = blockIdx.x * 256 + threadIdx.x;
    if (idx >= CI * NLAT_O * NLON_O) return;
    int p  = idx % NLON_O;
    int tt = (idx / NLON_O) % NLAT_O;
    int i  = idx / (NLON_O * NLAT_O);

    float theta = (float)tt * (PI_F / 360.0f);
    float post  = theta / (PI_F / 239.0f);
    float fi0 = floorf(post);
    int i0 = (int)fi0; i0 = min(max(i0, 0), NLAT_I - 1);
    int i1 = min(i0 + 1, NLAT_I - 1);
    float wt = post - (float)i0;

    float posp = ((float)p * (TWO_PI_F / (float)NLON_O)) / (TWO_PI_F / (float)NLON_I);
    float fj0 = floorf(posp);
    int j0 = ((int)fj0) % NLON_I;
    int j1 = j0 + 1; if (j1 >= NLON_I) j1 = 0;
    float wp = posp - fj0;

    const float* xi = x + i * (NLAT_I * NLON_I);
    float a  = xi[i0 * NLON_I + j0];
    float b  = xi[i0 * NLON_I + j1];
    float c  = xi[i1 * NLON_I + j0];
    float dv = xi[i1 * NLON_I + j1];
    float xl0 = (1.0f - wt) * a + wt * c;
    float xl1 = (1.0f - wt) * b + wt * dv;
    float val = (1.0f - wp) * xl0 + wp * xl1;

    g_xu4[(((i >> 2) * NLAT_O + tt) * NLON_O + p) * 4 + (i & 3)] = val;
}

// ---------------- kernel B: build psi + bounds (m, m2, m1) ----------------
__global__ void build_psi_kernel() {
    int d = blockIdx.x;
    int t = blockIdx.y;
    int tid = threadIdx.x;

    int lt = t + d - WOFF;
    bool valid = (lt >= 0) && (lt <= NLAT_O - 1);
    int ltc = min(max(lt, 0), NLAT_O - 1);

    float tht = (float)t   * (PI_F / 360.0f);
    float thi = (float)ltc * (PI_F / 360.0f);
    float ca = cosf(tht), sa = sinf(tht);
    float cg = cosf(thi), sg = sinf(thi);
    float A = ca * cg;
    float B = sa * sg;
    float cosc = cosf(CUTOFF_F);

    int m;
    if (!valid)                 m = -1;
    else if (A - B >= cosc)     m = 360;
    else if (A + B <  cosc)     m = -1;
    else {
        float ratio = (cosc - A) / fmaxf(B, 1e-30f);
        ratio = fminf(fmaxf(ratio, -1.0f), 1.0f);
        m = (int)floorf(acosf(ratio) * (360.0f / PI_F)) + 2;
        if (m > 360) m = 360;
    }

    // m2: expanded band where k0..k3 may be nonzero (r <= 2dr), margin grows band (safe)
    float cosc2i = cosf(2.0f * DR_F);
    float cosc2o = cosf(2.0f * DR_F + 1e-4f);
    int m2;
    if (m < 0)                   m2 = -1;
    else if (A - B >= cosc2i)    m2 = 360;
    else if (A + B <  cosc2o)    m2 = -1;
    else {
        float ratio = (cosc2o - A) / fmaxf(B, 1e-30f);
        ratio = fminf(fmaxf(ratio, -1.0f), 1.0f);
        m2 = (int)floorf(acosf(ratio) * (360.0f / PI_F)) + 3;
        if (m2 > 360) m2 = 360;
    }

    // m1: shrunken band where shell (k4..k6) is provably zero (r < dr), margin shrinks band (safe)
    float cosc1 = cosf(DR_F - 1e-4f);
    int m1;
    if (m < 0)                   m1 = -1;
    else if (A - B >= cosc1)     m1 = 360;
    else if (A + B <  cosc1)     m1 = -1;
    else {
        float ratio = (cosc1 - A) / fmaxf(B, 1e-30f);
        ratio = fminf(fmaxf(ratio, -1.0f), 1.0f);
        m1 = (int)floorf(acosf(ratio) * (360.0f / PI_F)) - 2;
        if (m1 > 360) m1 = 360;
        if (m1 < 0)   m1 = -1;
    }
    if (tid == 0) { g_m[t * 21 + d] = m; g_m2[t * 21 + d] = m2; g_m1[t * 21 + d] = m1; }

    float dth = (float)(ltc - t) * (PI_F / 360.0f);
    float shd = sinf(0.5f * dth);
    float hav_lat = shd * shd;

    float sums[7] = {0.f, 0.f, 0.f, 0.f, 0.f, 0.f, 0.f};
    if (m >= 0) {
        float qfac = sg * (PI_F / 360.0f) * (PI_F / 360.0f);
        int cnt = 2 * m + 1;
        for (int s = tid; s < cnt; s += 256) {
            int pp = s - m; if (pp < 0) pp += NLON_O;
            float beta = (float)pp * (TWO_PI_F / (float)NLON_O);
            float cb = cosf(beta), sb = sinf(beta);
            float z = A + cb * B;
            z = fminf(fmaxf(z, -1.0f), 1.0f);
            float r_acos = acosf(z);
            float mask = (r_acos <= CUTOFF_F) ? qfac : 0.0f;
            float sbh = sinf(0.5f * beta);
            float h = hav_lat + B * sbh * sbh;
            float r = 2.0f * asinf(fminf(sqrtf(fmaxf(h, 0.0f)), 1.0f));

            float xx = ca * cb * sg - sa * cg;
            float yy = sb * sg;
            float phi = atan2f(yy, xx);
            if (phi < 0.0f) phi += TWO_PI_F;

            float v[7];
            v[0] = fmaxf(0.0f, 1.0f - r * (1.0f / DR_F)) * mask;
            #pragma unroll
            for (int k = 1; k < 7; ++k) {
                int ir = (k - 1) / 3 + 1;
                int ip = (k - 1) % 3;
                float rad = fmaxf(0.0f, 1.0f - fabsf(r - (float)ir * DR_F) * (1.0f / DR_F));
                float dd  = fabsf(phi - (float)ip * DPH_F);
                dd = fminf(dd, TWO_PI_F - dd);
                float az = fmaxf(0.0f, 1.0f - dd * (1.0f / DPH_F));
                v[k] = rad * az * mask;
            }
            size_t b8 = ((size_t)(t * 21 + d) * 728 + s) * 8;
            #pragma unroll
            for (int k = 0; k < 7; ++k) g_psi8[b8 + k] = v[k];
            g_psi8[b8 + 7] = 0.0f;
            #pragma unroll
            for (int k = 0; k < 7; ++k) sums[k] += v[k];
        }
    }

    __shared__ float red[8][7];
    int lane = tid & 31, w = tid >> 5;
    #pragma unroll
    for (int k = 0; k < 7; ++k) {
        float s = sums[k];
        #pragma unroll
        for (int o = 16; o > 0; o >>= 1) s += __shfl_down_sync(0xffffffffu, s, o);
        if (lane == 0) red[w][k] = s;
    }
    __syncthreads();
    if (tid < 7) {
        float s = 0.0f;
        #pragma unroll
        for (int ww = 0; ww < 8; ++ww) s += red[ww][tid];
        g_sp[(tid * 361 + t) * 21 + d] = s;
    }
}

// ---------------- kernel INV ----------------
__global__ void inv_kernel() {
    int i = blockIdx.x * blockDim.x + threadIdx.x;
    if (i < 7 * 361) {
        float s = 0.0f;
        #pragma unroll
        for (int d = 0; d < 21; ++d) s += g_sp[i * 21 + d];
        g_invsc[i] = 1.0f / fmaxf(s, 1e-8f);
    }
}

// ---------------- kernel PACK ----------------
__global__ void pack_kernel(const float* __restrict__ wgt) {
    int idx = blockIdx.x * 256 + threadIdx.x;
    if (idx < 32 * 112) {
        int o = idx / 112;
        int j = idx - o * 112;
        int k = j >> 4;
        int h = j & 15;
        g_w2[idx * 2 + 0] = wgt[(o * CI + 2 * h) * KK + k];
        g_w2[idx * 2 + 1] = wgt[(o * CI + 2 * h + 1) * KK + k];
    }
    if (idx < 361) {
        #pragma unroll
        for (int k = 0; k < 7; ++k) g_invs2[idx * 8 + k] = g_invsc[k * 361 + idx];
        g_invs2[idx * 8 + 7] = 0.0f;
    }
}

// ---------------- kernel C: conv + fused GEMM ----------------
// phase1 smem: xu float4[8][720] (92160B) + psi float[728][8] (23296B) = 115456B
// phase2 (aliased): z2 float[112][64][2] = 57344B
#define SMEM_C (8 * 720 * 16 + 728 * 8 * 4)

#define PDUP(dst, v)     asm("mov.b64 %0,{%1,%1};" : "=l"(dst) : "f"(v))
#define UNP(lo, hi, v)   asm("mov.b64 {%0,%1},%2;" : "=f"(lo), "=f"(hi) : "l"(v))
#define F2(acc, p, x)    asm("fma.rn.f32x2 %0,%1,%2,%0;" : "+l"(acc) : "l"(p), "l"(x))
#define M2(acc, s)       asm("mul.rn.f32x2 %0,%0,%1;" : "+l"(acc) : "l"(s))

#define FMA_K(K, P)                                                      \
    F2(aK[K][0], P, v0.x); F2(aK[K][1], P, v0.y);                        \
    F2(aK[K][2], P, v1.x); F2(aK[K][3], P, v1.y);

// outer: shell only (k4,k5,k6)
#define BODY_OUT(Q, SS) {                                                \
    ulonglong2 v0 = xs0[Q];                                              \
    ulonglong2 v1 = xs1[Q];                                              \
    float k4s, k5s, k6s;                                                 \
    asm("ld.shared.v2.f32 {%0,%1},[%2];" : "=f"(k4s), "=f"(k5s)          \
        : "r"(psi_u + (unsigned)(SS) * 32u + 16u));                      \
    asm("ld.shared.f32 %0,[%1];" : "=f"(k6s)                             \
        : "r"(psi_u + (unsigned)(SS) * 32u + 24u));                      \
    u64 p4, p5, p6;                                                      \
    PDUP(p4, k4s); PDUP(p5, k5s); PDUP(p6, k6s);                         \
    FMA_K(4, p4) FMA_K(5, p5) FMA_K(6, p6) }

// innermost: k0..k3 only (shell provably zero)
#define BODY_IN4(Q, SS) {                                                \
    ulonglong2 v0 = xs0[Q];                                              \
    ulonglong2 v1 = xs1[Q];                                              \
    float k0s, k1s, k2s, k3s;                                            \
    asm("ld.shared.v2.f32 {%0,%1},[%2];" : "=f"(k0s), "=f"(k1s)          \
        : "r"(psi_u + (unsigned)(SS) * 32u));                            \
    asm("ld.shared.v2.f32 {%0,%1},[%2];" : "=f"(k2s), "=f"(k3s)          \
        : "r"(psi_u + (unsigned)(SS) * 32u + 8u));                       \
    u64 p0, p1, p2, p3;                                                  \
    PDUP(p0, k0s); PDUP(p1, k1s); PDUP(p2, k2s); PDUP(p3, k3s);          \
    FMA_K(0, p0) FMA_K(1, p1) FMA_K(2, p2) FMA_K(3, p3) }

// middle: all 7
#define BODY_MID(Q, SS) {                                                \
    ulonglong2 v0 = xs0[Q];                                              \
    ulonglong2 v1 = xs1[Q];                                              \
    float k0s, k1s, k2s, k3s, k4s, k5s, k6s;                             \
    asm("ld.shared.v2.f32 {%0,%1},[%2];" : "=f"(k0s), "=f"(k1s)          \
        : "r"(psi_u + (unsigned)(SS) * 32u));                            \
    asm("ld.shared.v2.f32 {%0,%1},[%2];" : "=f"(k2s), "=f"(k3s)          \
        : "r"(psi_u + (unsigned)(SS) * 32u + 8u));                       \
    asm("ld.shared.v2.f32 {%0,%1},[%2];" : "=f"(k4s), "=f"(k5s)          \
        : "r"(psi_u + (unsigned)(SS) * 32u + 16u));                      \
    asm("ld.shared.f32 %0,[%1];" : "=f"(k6s)                             \
        : "r"(psi_u + (unsigned)(SS) * 32u + 24u));                      \
    u64 p0, p1, p2, p3, p4, p5, p6;                                      \
    PDUP(p0, k0s); PDUP(p1, k1s); PDUP(p2, k2s); PDUP(p3, k3s);          \
    PDUP(p4, k4s); PDUP(p5, k5s); PDUP(p6, k6s);                         \
    FMA_K(0, p0) FMA_K(1, p1) FMA_K(2, p2) FMA_K(3, p3)                  \
    FMA_K(4, p4) FMA_K(5, p5) FMA_K(6, p6) }

__global__ void __launch_bounds__(256, 2)
conv_kernel(float* __restrict__ y) {
    extern __shared__ float sm[];
    float4* xu_s  = (float4*)sm;                        // [8][720]
    float*  psi_s = sm + 8 * 720 * 4;                   // [728][8]
    unsigned psi_u = (unsigned)__cvta_generic_to_shared(psi_s);

    int ty = blockIdx.y;
    int t  = (ty & 1) ? (360 - (ty >> 1)) : (ty >> 1);  // heavy rows first
    int p0 = blockIdx.x * 64;
    int tid  = threadIdx.x;
    int lane = tid & 31;
    int wpi  = tid >> 5;
    int sub  = wpi & 1;                                 // p-subtile
    int cg   = wpi >> 1;                                // channel octet
    int qb   = 32 * sub + lane;

    u64 aK[7][4];
    #pragma unroll
    for (int k = 0; k < 7; ++k)
        #pragma unroll
        for (int j = 0; j < 4; ++j) aK[k][j] = 0ull;

    const float4* gx = (const float4*)g_xu4;

    for (int d = 0; d < 21; ++d) {
        int lt = t + d - WOFF;
        if (lt < 0 || lt > 360) continue;
        int m = g_m[t * 21 + d];
        if (m < 0) continue;
        int m2 = g_m2[t * 21 + d];
        int m1 = g_m1[t * 21 + d];
        int cnt = 2 * m + 1;
        int L = 64 + 2 * m;
        int n = (L < 720) ? L : 720;
        int base = p0 - m;
        base %= 720; if (base < 0) base += 720;

        int oL, oR;
        if (m2 < 0) { oL = cnt; oR = cnt; }
        else { oL = max(0, m - m2); oR = min(cnt, m + m2 + 1); }
        int cL, cR;
        if (m1 < 0) { cL = oR; cR = oR; }
        else { cL = max(oL, m - m1); cR = min(oR, m + m1 + 1); }

        __syncthreads();
        // stage xu window: warp wpi stages group wpi
        {
            const float4* src = gx + ((size_t)wpi * NLAT_O + lt) * NLON_O;
            for (int q = lane; q < n; q += 32) {
                int lon = base + q; if (lon >= 720) lon -= 720;
                xu_s[wpi * 720 + q] = src[lon];
            }
        }
        // stage psi (pure copy, 32B per s-entry)
        {
            const float4* src = (const float4*)(g_psi8 + ((size_t)(t * 21 + d)) * 728 * 8);
            float4* dst = (float4*)psi_s;
            for (int s2 = tid; s2 < 2 * cnt; s2 += 256) dst[s2] = src[s2];
        }
        __syncthreads();

        int s = 0;
        if (n < 720) {
            const ulonglong2* xs0 = (const ulonglong2*)(xu_s + (2 * cg) * 720) + qb;
            const ulonglong2* xs1 = xs0 + 720;
            for (; s < oL; ++s) BODY_OUT(s, s)
            for (; s < cL; ++s) BODY_MID(s, s)
            for (; s < cR; ++s) BODY_IN4(s, s)
            for (; s < oR; ++s) BODY_MID(s, s)
            for (; s < cnt; ++s) BODY_OUT(s, s)
        } else {
            const ulonglong2* xs0 = (const ulonglong2*)(xu_s + (2 * cg) * 720);
            const ulonglong2* xs1 = xs0 + 720;
            int q = qb;
            for (; s < oL; ++s) { BODY_OUT(q, s) ++q; if (q >= 720) q -= 720; }
            for (; s < cL; ++s) { BODY_MID(q, s) ++q; if (q >= 720) q -= 720; }
            for (; s < cR; ++s) { BODY_IN4(q, s) ++q; if (q >= 720) q -= 720; }
            for (; s < oR; ++s) { BODY_MID(q, s) ++q; if (q >= 720) q -= 720; }
            for (; s < cnt; ++s) { BODY_OUT(q, s) ++q; if (q >= 720) q -= 720; }
        }
    }

    // ---- fold 1/scale ----
    {
        const float* iv = g_invs2 + t * 8;
        #pragma unroll
        for (int k = 0; k < 7; ++k) {
            u64 dk;
            PDUP(dk, iv[k]);
            #pragma unroll
            for (int j = 0; j < 4; ++j) M2(aK[k][j], dk);
        }
    }

    __syncthreads();
    // ---- phase 2: scatter z [112 kpair][64 p][2 par], GEMM ----
    u64* z2w = (u64*)sm;
    {
        #pragma unroll
        for (int k = 0; k < 7; ++k)
            #pragma unroll
            for (int j = 0; j < 4; ++j)
                z2w[(k * 16 + 4 * cg + j) * 64 + qb] = aK[k][j];
    }
    __syncthreads();

    // GEMM: thread = 2 adjacent p x 4 o
    int po2 = tid & 31;
    int og  = (tid >> 5) & 7;
    const ulonglong2* zp = (const ulonglong2*)z2w;
    const u64* wu = (const u64*)g_w2;

    u64 acc0[4], acc1[4];
    #pragma unroll
    for (int oo = 0; oo < 4; ++oo) { acc0[oo] = 0ull; acc1[oo] = 0ull; }

    for (int j = 0; j < 112; ++j) {
        ulonglong2 zv = zp[j * 32 + po2];
        #pragma unroll
        for (int oo = 0; oo < 4; ++oo) {
            u64 wv = __ldg(wu + (og + 8 * oo) * 112 + j);
            F2(acc0[oo], wv, zv.x);
            F2(acc1[oo], wv, zv.y);
        }
    }

    int pA0 = p0 + 2 * po2;
    int pA1 = pA0 + 1;
    #pragma unroll
    for (int oo = 0; oo < 4; ++oo) {
        int o = og + 8 * oo;
        float lo, hi;
        if (pA0 < 720) {
            UNP(lo, hi, acc0[oo]);
            y[((size_t)o * NLAT_O + t) * NLON_O + pA0] = lo + hi;
        }
        if (pA1 < 720) {
            UNP(lo, hi, acc1[oo]);
            y[((size_t)o * NLAT_O + t) * NLON_O + pA1] = lo + hi;
        }
    }
}

// ---------------- launcher ----------------
extern "C" void kernel_launch(void* const* d_in, const int* in_sizes, int n_in,
                              void* d_out, int out_size) {
    const float* x = (const float*)d_in[0];       // [1,32,240,480]
    const float* w = (const float*)d_in[1];       // [32,32,7]
    float* y = (float*)d_out;                     // [1,32,361,720]

    cudaFuncSetAttribute(conv_kernel, cudaFuncAttributeMaxDynamicSharedMemorySize, SMEM_C);

    int nA = CI * NLAT_O * NLON_O;
    upsample_kernel<<<(nA + 255) / 256, 256>>>(x);
    build_psi_kernel<<<dim3(21, 361), 256>>>();
    inv_kernel<<<(7 * 361 + 255) / 256, 256>>>();
    pack_kernel<<<(32 * 112 + 255) / 256, 256>>>(w);
    conv_kernel<<<dim3(12, 361), 256, SMEM_C>>>(y);
}

// round 13
// speedup vs baseline: 1.6284x; 1.0069x over previous
#include <cuda_runtime.h>

#define NLAT_I 240
#define NLON_I 480
#define NLAT_O 361
#define NLON_O 720
#define CI     32
#define CO     32
#define KK     7
#define WOFF   10

#define PI_F      3.14159265358979323846f
#define TWO_PI_F  6.28318530717958647692f
#define CUTOFF_F  0.08508480103472356f
#define DR_F      0.028361600344907855f
#define DPH_F     2.0943951023931953f

typedef unsigned long long u64;

// ---------------- device scratch ----------------
static __device__ float g_xu4[8 * 361 * 720 * 4];                  // [g][t][p] float4 (ch 4g..4g+3)
static __device__ float g_psi8[(size_t)361 * 21 * 728 * 8];        // [t][d][s][8] = k0..k6, pad
static __device__ float g_sp[7 * 361 * 21];
static __device__ float g_invsc[7 * 361];
static __device__ float g_invs2[361 * 8];                          // (i0..i6,0) per t
static __device__ float g_w2[32 * 112 * 2];                        // packed weight pairs
static __device__ int   g_m[361 * 21];
static __device__ int   g_m2[361 * 21];
static __device__ int   g_m1[361 * 21];

// ---------------- kernel A: bilinear upsample ----------------
__global__ void upsample_kernel(const float* __restrict__ x) {
    int idx = blockIdx.x * 256 + threadIdx.x;
    if (idx >= CI * NLAT_O * NLON_O) return;
    int p  = idx % NLON_O;
    int tt = (idx / NLON_O) % NLAT_O;
    int i  = idx / (NLON_O * NLAT_O);

    float theta = (float)tt * (PI_F / 360.0f);
    float post  = theta / (PI_F / 239.0f);
    float fi0 = floorf(post);
    int i0 = (int)fi0; i0 = min(max(i0, 0), NLAT_I - 1);
    int i1 = min(i0 + 1, NLAT_I - 1);
    float wt = post - (float)i0;

    float posp = ((float)p * (TWO_PI_F / (float)NLON_O)) / (TWO_PI_F / (float)NLON_I);
    float fj0 = floorf(posp);
    int j0 = ((int)fj0) % NLON_I;
    int j1 = j0 + 1; if (j1 >= NLON_I) j1 = 0;
    float wp = posp - fj0;

    const float* xi = x + i * (NLAT_I * NLON_I);
    float a  = xi[i0 * NLON_I + j0];
    float b  = xi[i0 * NLON_I + j1];
    float c  = xi[i1 * NLON_I + j0];
    float dv = xi[i1 * NLON_I + j1];
    float xl0 = (1.0f - wt) * a + wt * c;
    float xl1 = (1.0f - wt) * b + wt * dv;
    float val = (1.0f - wp) * xl0 + wp * xl1;

    g_xu4[(((i >> 2) * NLAT_O + tt) * NLON_O + p) * 4 + (i & 3)] = val;
}

// ---------------- kernel B: build psi + bounds (m, m2, m1) ----------------
__global__ void build_psi_kernel() {
    int d = blockIdx.x;
    int t = blockIdx.y;
    int tid = threadIdx.x;

    int lt = t + d - WOFF;
    bool valid = (lt >= 0) && (lt <= NLAT_O - 1);
    int ltc = min(max(lt, 0), NLAT_O - 1);

    float tht = (float)t   * (PI_F / 360.0f);
    float thi = (float)ltc * (PI_F / 360.0f);
    float ca = cosf(tht), sa = sinf(tht);
    float cg = cosf(thi), sg = sinf(thi);
    float A = ca * cg;
    float B = sa * sg;
    float cosc = cosf(CUTOFF_F);

    int m;
    if (!valid)                 m = -1;
    else if (A - B >= cosc)     m = 360;
    else if (A + B <  cosc)     m = -1;
    else {
        float ratio = (cosc - A) / fmaxf(B, 1e-30f);
        ratio = fminf(fmaxf(ratio, -1.0f), 1.0f);
        m = (int)floorf(acosf(ratio) * (360.0f / PI_F)) + 2;
        if (m > 360) m = 360;
    }

    // m2: expanded band where k0..k3 may be nonzero (r <= 2dr)
    float cosc2i = cosf(2.0f * DR_F);
    float cosc2o = cosf(2.0f * DR_F + 1e-4f);
    int m2;
    if (m < 0)                   m2 = -1;
    else if (A - B >= cosc2i)    m2 = 360;
    else if (A + B <  cosc2o)    m2 = -1;
    else {
        float ratio = (cosc2o - A) / fmaxf(B, 1e-30f);
        ratio = fminf(fmaxf(ratio, -1.0f), 1.0f);
        m2 = (int)floorf(acosf(ratio) * (360.0f / PI_F)) + 3;
        if (m2 > 360) m2 = 360;
    }

    // m1: shrunken band where shell (k4..k6) is provably zero (r < dr)
    float cosc1 = cosf(DR_F - 1e-4f);
    int m1;
    if (m < 0)                   m1 = -1;
    else if (A - B >= cosc1)     m1 = 360;
    else if (A + B <  cosc1)     m1 = -1;
    else {
        float ratio = (cosc1 - A) / fmaxf(B, 1e-30f);
        ratio = fminf(fmaxf(ratio, -1.0f), 1.0f);
        m1 = (int)floorf(acosf(ratio) * (360.0f / PI_F)) - 2;
        if (m1 > 360) m1 = 360;
        if (m1 < 0)   m1 = -1;
    }
    if (tid == 0) { g_m[t * 21 + d] = m; g_m2[t * 21 + d] = m2; g_m1[t * 21 + d] = m1; }

    float dth = (float)(ltc - t) * (PI_F / 360.0f);
    float shd = sinf(0.5f * dth);
    float hav_lat = shd * shd;

    float sums[7] = {0.f, 0.f, 0.f, 0.f, 0.f, 0.f, 0.f};
    if (m >= 0) {
        float qfac = sg * (PI_F / 360.0f) * (PI_F / 360.0f);
        int cnt = 2 * m + 1;
        for (int s = tid; s < cnt; s += 256) {
            int pp = s - m; if (pp < 0) pp += NLON_O;
            float beta = (float)pp * (TWO_PI_F / (float)NLON_O);
            float cb = cosf(beta), sb = sinf(beta);
            float z = A + cb * B;
            z = fminf(fmaxf(z, -1.0f), 1.0f);
            float r_acos = acosf(z);
            float mask = (r_acos <= CUTOFF_F) ? qfac : 0.0f;
            float sbh = sinf(0.5f * beta);
            float h = hav_lat + B * sbh * sbh;
            float r = 2.0f * asinf(fminf(sqrtf(fmaxf(h, 0.0f)), 1.0f));

            float xx = ca * cb * sg - sa * cg;
            float yy = sb * sg;
            float phi = atan2f(yy, xx);
            if (phi < 0.0f) phi += TWO_PI_F;

            float v[7];
            v[0] = fmaxf(0.0f, 1.0f - r * (1.0f / DR_F)) * mask;
            #pragma unroll
            for (int k = 1; k < 7; ++k) {
                int ir = (k - 1) / 3 + 1;
                int ip = (k - 1) % 3;
                float rad = fmaxf(0.0f, 1.0f - fabsf(r - (float)ir * DR_F) * (1.0f / DR_F));
                float dd  = fabsf(phi - (float)ip * DPH_F);
                dd = fminf(dd, TWO_PI_F - dd);
                float az = fmaxf(0.0f, 1.0f - dd * (1.0f / DPH_F));
                v[k] = rad * az * mask;
            }
            size_t b8 = ((size_t)(t * 21 + d) * 728 + s) * 8;
            #pragma unroll
            for (int k = 0; k < 7; ++k) g_psi8[b8 + k] = v[k];
            g_psi8[b8 + 7] = 0.0f;
            #pragma unroll
            for (int k = 0; k < 7; ++k) sums[k] += v[k];
        }
    }

    __shared__ float red[8][7];
    int lane = tid & 31, w = tid >> 5;
    #pragma unroll
    for (int k = 0; k < 7; ++k) {
        float s = sums[k];
        #pragma unroll
        for (int o = 16; o > 0; o >>= 1) s += __shfl_down_sync(0xffffffffu, s, o);
        if (lane == 0) red[w][k] = s;
    }
    __syncthreads();
    if (tid < 7) {
        float s = 0.0f;
        #pragma unroll
        for (int ww = 0; ww < 8; ++ww) s += red[ww][tid];
        g_sp[(tid * 361 + t) * 21 + d] = s;
    }
}

// ---------------- kernel INV ----------------
__global__ void inv_kernel() {
    int i = blockIdx.x * blockDim.x + threadIdx.x;
    if (i < 7 * 361) {
        float s = 0.0f;
        #pragma unroll
        for (int d = 0; d < 21; ++d) s += g_sp[i * 21 + d];
        g_invsc[i] = 1.0f / fmaxf(s, 1e-8f);
    }
}

// ---------------- kernel PACK ----------------
__global__ void pack_kernel(const float* __restrict__ wgt) {
    int idx = blockIdx.x * 256 + threadIdx.x;
    if (idx < 32 * 112) {
        int o = idx / 112;
        int j = idx - o * 112;
        int k = j >> 4;
        int h = j & 15;
        g_w2[idx * 2 + 0] = wgt[(o * CI + 2 * h) * KK + k];
        g_w2[idx * 2 + 1] = wgt[(o * CI + 2 * h + 1) * KK + k];
    }
    if (idx < 361) {
        #pragma unroll
        for (int k = 0; k < 7; ++k) g_invs2[idx * 8 + k] = g_invsc[k * 361 + idx];
        g_invs2[idx * 8 + 7] = 0.0f;
    }
}

// ---------------- kernel C: conv + fused GEMM ----------------
// phase1 smem: xu float4[8][720] (92160B) + psi float[728][8] (23296B) = 115456B
// phase2 (aliased): z2 float[112][64][2] = 57344B
#define SMEM_C (8 * 720 * 16 + 728 * 8 * 4)

#define PDUP(dst, v)     asm("mov.b64 %0,{%1,%1};" : "=l"(dst) : "f"(v))
#define UNP(lo, hi, v)   asm("mov.b64 {%0,%1},%2;" : "=f"(lo), "=f"(hi) : "l"(v))
#define F2(acc, p, x)    asm("fma.rn.f32x2 %0,%1,%2,%0;" : "+l"(acc) : "l"(p), "l"(x))
#define M2(acc, s)       asm("mul.rn.f32x2 %0,%0,%1;" : "+l"(acc) : "l"(s))

#define FMA_K(K, P)                                                      \
    F2(aK[K][0], P, v0.x); F2(aK[K][1], P, v0.y);                        \
    F2(aK[K][2], P, v1.x); F2(aK[K][3], P, v1.y);

// outer: shell only (k4,k5,k6) — one v4 load
#define BODY_OUT(Q, SS) {                                                \
    ulonglong2 v0 = xs0[Q];                                              \
    ulonglong2 v1 = xs1[Q];                                              \
    float k4s, k5s, k6s, kjs;                                            \
    asm("ld.shared.v4.f32 {%0,%1,%2,%3},[%4];"                           \
        : "=f"(k4s), "=f"(k5s), "=f"(k6s), "=f"(kjs)                     \
        : "r"(psi_u + (unsigned)(SS) * 32u + 16u));                      \
    u64 p4, p5, p6;                                                      \
    PDUP(p4, k4s); PDUP(p5, k5s); PDUP(p6, k6s);                         \
    FMA_K(4, p4) FMA_K(5, p5) FMA_K(6, p6) }

// innermost: k0..k3 only — one v4 load
#define BODY_IN4(Q, SS) {                                                \
    ulonglong2 v0 = xs0[Q];                                              \
    ulonglong2 v1 = xs1[Q];                                              \
    float k0s, k1s, k2s, k3s;                                            \
    asm("ld.shared.v4.f32 {%0,%1,%2,%3},[%4];"                           \
        : "=f"(k0s), "=f"(k1s), "=f"(k2s), "=f"(k3s)                     \
        : "r"(psi_u + (unsigned)(SS) * 32u));                            \
    u64 p0, p1, p2, p3;                                                  \
    PDUP(p0, k0s); PDUP(p1, k1s); PDUP(p2, k2s); PDUP(p3, k3s);          \
    FMA_K(0, p0) FMA_K(1, p1) FMA_K(2, p2) FMA_K(3, p3) }

// middle: all 7 — two v4 loads
#define BODY_MID(Q, SS) {                                                \
    ulonglong2 v0 = xs0[Q];                                              \
    ulonglong2 v1 = xs1[Q];                                              \
    float k0s, k1s, k2s, k3s, k4s, k5s, k6s, kjs;                        \
    asm("ld.shared.v4.f32 {%0,%1,%2,%3},[%4];"                           \
        : "=f"(k0s), "=f"(k1s), "=f"(k2s), "=f"(k3s)                     \
        : "r"(psi_u + (unsigned)(SS) * 32u));                            \
    asm("ld.shared.v4.f32 {%0,%1,%2,%3},[%4];"                           \
        : "=f"(k4s), "=f"(k5s), "=f"(k6s), "=f"(kjs)                     \
        : "r"(psi_u + (unsigned)(SS) * 32u + 16u));                      \
    u64 p0, p1, p2, p3, p4, p5, p6;                                      \
    PDUP(p0, k0s); PDUP(p1, k1s); PDUP(p2, k2s); PDUP(p3, k3s);          \
    PDUP(p4, k4s); PDUP(p5, k5s); PDUP(p6, k6s);                         \
    FMA_K(0, p0) FMA_K(1, p1) FMA_K(2, p2) FMA_K(3, p3)                  \
    FMA_K(4, p4) FMA_K(5, p5) FMA_K(6, p6) }

// unrolled-by-2 band loop (linear path)
#define BAND2_LIN(BODY, END)                                             \
    for (; s + 1 < (END); s += 2) { BODY(s, s) BODY(s + 1, s + 1) }      \
    if (s < (END)) { BODY(s, s) ++s; }

// unrolled-by-2 band loop (wrap path)
#define BAND2_WRAP(BODY, END)                                            \
    for (; s + 1 < (END); s += 2) {                                      \
        int q1 = q + 1; if (q1 >= 720) q1 -= 720;                        \
        BODY(q, s) BODY(q1, s + 1)                                       \
        q = q1 + 1; if (q >= 720) q -= 720;                              \
    }                                                                    \
    if (s < (END)) { BODY(q, s) ++s; ++q; if (q >= 720) q -= 720; }

__global__ void __launch_bounds__(256, 2)
conv_kernel(float* __restrict__ y) {
    extern __shared__ float sm[];
    float4* xu_s  = (float4*)sm;                        // [8][720]
    float*  psi_s = sm + 8 * 720 * 4;                   // [728][8]
    unsigned psi_u = (unsigned)__cvta_generic_to_shared(psi_s);

    int ty = blockIdx.y;
    int t  = (ty & 1) ? (360 - (ty >> 1)) : (ty >> 1);  // heavy rows first
    int p0 = blockIdx.x * 64;
    int tid  = threadIdx.x;
    int lane = tid & 31;
    int wpi  = tid >> 5;
    int sub  = wpi & 1;                                 // p-subtile
    int cg   = wpi >> 1;                                // channel octet
    int qb   = 32 * sub + lane;

    u64 aK[7][4];
    #pragma unroll
    for (int k = 0; k < 7; ++k)
        #pragma unroll
        for (int j = 0; j < 4; ++j) aK[k][j] = 0ull;

    const float4* gx = (const float4*)g_xu4;

    for (int d = 0; d < 21; ++d) {
        int lt = t + d - WOFF;
        if (lt < 0 || lt > 360) continue;
        int m = g_m[t * 21 + d];
        if (m < 0) continue;
        int m2 = g_m2[t * 21 + d];
        int m1 = g_m1[t * 21 + d];
        int cnt = 2 * m + 1;
        int L = 64 + 2 * m;
        int n = (L < 720) ? L : 720;
        int base = p0 - m;
        base %= 720; if (base < 0) base += 720;

        int oL, oR;
        if (m2 < 0) { oL = cnt; oR = cnt; }
        else { oL = max(0, m - m2); oR = min(cnt, m + m2 + 1); }
        int cL, cR;
        if (m1 < 0) { cL = oR; cR = oR; }
        else { cL = max(oL, m - m1); cR = min(oR, m + m1 + 1); }

        __syncthreads();
        // stage xu window: warp wpi stages group wpi
        {
            const float4* src = gx + ((size_t)wpi * NLAT_O + lt) * NLON_O;
            for (int q = lane; q < n; q += 32) {
                int lon = base + q; if (lon >= 720) lon -= 720;
                xu_s[wpi * 720 + q] = src[lon];
            }
        }
        // stage psi (pure copy, 32B per s-entry)
        {
            const float4* src = (const float4*)(g_psi8 + ((size_t)(t * 21 + d)) * 728 * 8);
            float4* dst = (float4*)psi_s;
            for (int s2 = tid; s2 < 2 * cnt; s2 += 256) dst[s2] = src[s2];
        }
        __syncthreads();

        int s = 0;
        if (n < 720) {
            const ulonglong2* xs0 = (const ulonglong2*)(xu_s + (2 * cg) * 720) + qb;
            const ulonglong2* xs1 = xs0 + 720;
            BAND2_LIN(BODY_OUT, oL)
            BAND2_LIN(BODY_MID, cL)
            BAND2_LIN(BODY_IN4, cR)
            BAND2_LIN(BODY_MID, oR)
            BAND2_LIN(BODY_OUT, cnt)
        } else {
            const ulonglong2* xs0 = (const ulonglong2*)(xu_s + (2 * cg) * 720);
            const ulonglong2* xs1 = xs0 + 720;
            int q = qb;
            BAND2_WRAP(BODY_OUT, oL)
            BAND2_WRAP(BODY_MID, cL)
            BAND2_WRAP(BODY_IN4, cR)
            BAND2_WRAP(BODY_MID, oR)
            BAND2_WRAP(BODY_OUT, cnt)
        }
    }

    // ---- fold 1/scale ----
    {
        const float* iv = g_invs2 + t * 8;
        #pragma unroll
        for (int k = 0; k < 7; ++k) {
            u64 dk;
            PDUP(dk, iv[k]);
            #pragma unroll
            for (int j = 0; j < 4; ++j) M2(aK[k][j], dk);
        }
    }

    __syncthreads();
    // ---- phase 2: scatter z [112 kpair][64 p][2 par], GEMM ----
    u64* z2w = (u64*)sm;
    {
        #pragma unroll
        for (int k = 0; k < 7; ++k)
            #pragma unroll
            for (int j = 0; j < 4; ++j)
                z2w[(k * 16 + 4 * cg + j) * 64 + qb] = aK[k][j];
    }
    __syncthreads();

    // GEMM: thread = 2 adjacent p x 4 o
    int po2 = tid & 31;
    int og  = (tid >> 5) & 7;
    const ulonglong2* zp = (const ulonglong2*)z2w;
    const u64* wu = (const u64*)g_w2;

    u64 acc0[4], acc1[4];
    #pragma unroll
    for (int oo = 0; oo < 4; ++oo) { acc0[oo] = 0ull; acc1[oo] = 0ull; }

    for (int j = 0; j < 112; ++j) {
        ulonglong2 zv = zp[j * 32 + po2];
        #pragma unroll
        for (int oo = 0; oo < 4; ++oo) {
            u64 wv = __ldg(wu + (og + 8 * oo) * 112 + j);
            F2(acc0[oo], wv, zv.x);
            F2(acc1[oo], wv, zv.y);
        }
    }

    int pA0 = p0 + 2 * po2;
    int pA1 = pA0 + 1;
    #pragma unroll
    for (int oo = 0; oo < 4; ++oo) {
        int o = og + 8 * oo;
        float lo, hi;
        if (pA0 < 720) {
            UNP(lo, hi, acc0[oo]);
            y[((size_t)o * NLAT_O + t) * NLON_O + pA0] = lo + hi;
        }
        if (pA1 < 720) {
            UNP(lo, hi, acc1[oo]);
            y[((size_t)o * NLAT_O + t) * NLON_O + pA1] = lo + hi;
        }
    }
}

// ---------------- launcher ----------------
extern "C" void kernel_launch(void* const* d_in, const int* in_sizes, int n_in,
                              void* d_out, int out_size) {
    const float* x = (const float*)d_in[0];       // [1,32,240,480]
    const float* w = (const float*)d_in[1];       // [32,32,7]
    float* y = (float*)d_out;                     // [1,32,361,720]

    cudaFuncSetAttribute(conv_kernel, cudaFuncAttributeMaxDynamicSharedMemorySize, SMEM_C);

    int nA = CI * NLAT_O * NLON_O;
    upsample_kernel<<<(nA + 255) / 256, 256>>>(x);
    build_psi_kernel<<<dim3(21, 361), 256>>>();
    inv_kernel<<<(7 * 361 + 255) / 256, 256>>>();
    pack_kernel<<<(32 * 112 + 255) / 256, 256>>>(w);
    conv_kernel<<<dim3(12, 361), 256, SMEM_C>>>(y);
}

// round 14
// speedup vs baseline: 1.6924x; 1.0393x over previous
#include <cuda_runtime.h>

#define NLAT_I 240
#define NLON_I 480
#define NLAT_O 361
#define NLON_O 720
#define CI     32
#define CO     32
#define KK     7
#define WOFF   10

#define PI_F      3.14159265358979323846f
#define TWO_PI_F  6.28318530717958647692f
#define CUTOFF_F  0.08508480103472356f
#define DR_F      0.028361600344907855f
#define DPH_F     2.0943951023931953f

typedef unsigned long long u64;

// psi slot layout: [0]=k1 [1]=k2 [2]=k3 [3]=k6 [4]=k4 [5]=k5 [6]=k0 [7]=0
// ---------------- device scratch ----------------
static __device__ float g_xu4[8 * 361 * 720 * 4];                  // [g][t][p] float4 (ch 4g..4g+3)
static __device__ float g_psi8[(size_t)361 * 21 * 728 * 8];        // [t][d][s][8] slots
static __device__ float g_sp[7 * 361 * 21];
static __device__ float g_invs2[361 * 8];                          // per-t 1/scale in SLOT order
static __device__ float g_w2[32 * 112 * 2];                        // packed weight pairs
static __device__ int   g_m[361 * 21];
static __device__ int   g_m2[361 * 21];
static __device__ int   g_m1[361 * 21];                            // shrunk: shell provably 0 inside
static __device__ int   g_m1g[361 * 21];                           // grown:  k0 provably 0 outside

// ---------------- kernel A: bilinear upsample ----------------
__global__ void upsample_kernel(const float* __restrict__ x) {
    int idx = blockIdx.x * 256 + threadIdx.x;
    if (idx >= CI * NLAT_O * NLON_O) return;
    int p  = idx % NLON_O;
    int tt = (idx / NLON_O) % NLAT_O;
    int i  = idx / (NLON_O * NLAT_O);

    float theta = (float)tt * (PI_F / 360.0f);
    float post  = theta / (PI_F / 239.0f);
    float fi0 = floorf(post);
    int i0 = (int)fi0; i0 = min(max(i0, 0), NLAT_I - 1);
    int i1 = min(i0 + 1, NLAT_I - 1);
    float wt = post - (float)i0;

    float posp = ((float)p * (TWO_PI_F / (float)NLON_O)) / (TWO_PI_F / (float)NLON_I);
    float fj0 = floorf(posp);
    int j0 = ((int)fj0) % NLON_I;
    int j1 = j0 + 1; if (j1 >= NLON_I) j1 = 0;
    float wp = posp - fj0;

    const float* xi = x + i * (NLAT_I * NLON_I);
    float a  = xi[i0 * NLON_I + j0];
    float b  = xi[i0 * NLON_I + j1];
    float c  = xi[i1 * NLON_I + j0];
    float dv = xi[i1 * NLON_I + j1];
    float xl0 = (1.0f - wt) * a + wt * c;
    float xl1 = (1.0f - wt) * b + wt * dv;
    float val = (1.0f - wp) * xl0 + wp * xl1;

    g_xu4[(((i >> 2) * NLAT_O + tt) * NLON_O + p) * 4 + (i & 3)] = val;
}

// ---------------- kernel B: build psi (slot layout) + bounds ----------------
__global__ void build_psi_kernel() {
    int d = blockIdx.x;
    int t = blockIdx.y;
    int tid = threadIdx.x;

    int lt = t + d - WOFF;
    bool valid = (lt >= 0) && (lt <= NLAT_O - 1);
    int ltc = min(max(lt, 0), NLAT_O - 1);

    float tht = (float)t   * (PI_F / 360.0f);
    float thi = (float)ltc * (PI_F / 360.0f);
    float ca = cosf(tht), sa = sinf(tht);
    float cg = cosf(thi), sg = sinf(thi);
    float A = ca * cg;
    float B = sa * sg;
    float cosc = cosf(CUTOFF_F);

    int m;
    if (!valid)                 m = -1;
    else if (A - B >= cosc)     m = 360;
    else if (A + B <  cosc)     m = -1;
    else {
        float ratio = (cosc - A) / fmaxf(B, 1e-30f);
        ratio = fminf(fmaxf(ratio, -1.0f), 1.0f);
        m = (int)floorf(acosf(ratio) * (360.0f / PI_F)) + 2;
        if (m > 360) m = 360;
    }

    // m2: grown band where k0..k3 may be nonzero (r <= 2dr)
    float cosc2i = cosf(2.0f * DR_F);
    float cosc2o = cosf(2.0f * DR_F + 1e-4f);
    int m2;
    if (m < 0)                   m2 = -1;
    else if (A - B >= cosc2i)    m2 = 360;
    else if (A + B <  cosc2o)    m2 = -1;
    else {
        float ratio = (cosc2o - A) / fmaxf(B, 1e-30f);
        ratio = fminf(fmaxf(ratio, -1.0f), 1.0f);
        m2 = (int)floorf(acosf(ratio) * (360.0f / PI_F)) + 3;
        if (m2 > 360) m2 = 360;
    }

    // m1 (shrunk): inside this, shell (k4..k6) provably zero (r < dr)
    float cosc1 = cosf(DR_F - 1e-4f);
    int m1;
    if (m < 0)                   m1 = -1;
    else if (A - B >= cosc1)     m1 = 360;
    else if (A + B <  cosc1)     m1 = -1;
    else {
        float ratio = (cosc1 - A) / fmaxf(B, 1e-30f);
        ratio = fminf(fmaxf(ratio, -1.0f), 1.0f);
        m1 = (int)floorf(acosf(ratio) * (360.0f / PI_F)) - 2;
        if (m1 > 360) m1 = 360;
        if (m1 < 0)   m1 = -1;
    }

    // m1g (grown): outside this, k0 provably zero (r > dr)
    float c1g_hi = cosf(DR_F);
    float c1g_lo = cosf(DR_F + 1e-4f);
    int m1g;
    if (m < 0)                   m1g = -1;
    else if (A - B >= c1g_hi)    m1g = 360;
    else if (A + B <  c1g_lo)    m1g = -1;
    else {
        float ratio = (c1g_lo - A) / fmaxf(B, 1e-30f);
        ratio = fminf(fmaxf(ratio, -1.0f), 1.0f);
        m1g = (int)floorf(acosf(ratio) * (360.0f / PI_F)) + 2;
        if (m1g > 360) m1g = 360;
    }
    if (tid == 0) {
        g_m[t * 21 + d] = m; g_m2[t * 21 + d] = m2;
        g_m1[t * 21 + d] = m1; g_m1g[t * 21 + d] = m1g;
    }

    float dth = (float)(ltc - t) * (PI_F / 360.0f);
    float shd = sinf(0.5f * dth);
    float hav_lat = shd * shd;

    float sums[7] = {0.f, 0.f, 0.f, 0.f, 0.f, 0.f, 0.f};
    if (m >= 0) {
        float qfac = sg * (PI_F / 360.0f) * (PI_F / 360.0f);
        int cnt = 2 * m + 1;
        for (int s = tid; s < cnt; s += 256) {
            int pp = s - m; if (pp < 0) pp += NLON_O;
            float beta = (float)pp * (TWO_PI_F / (float)NLON_O);
            float cb = cosf(beta), sb = sinf(beta);
            float z = A + cb * B;
            z = fminf(fmaxf(z, -1.0f), 1.0f);
            float r_acos = acosf(z);
            float mask = (r_acos <= CUTOFF_F) ? qfac : 0.0f;
            float sbh = sinf(0.5f * beta);
            float h = hav_lat + B * sbh * sbh;
            float r = 2.0f * asinf(fminf(sqrtf(fmaxf(h, 0.0f)), 1.0f));

            float xx = ca * cb * sg - sa * cg;
            float yy = sb * sg;
            float phi = atan2f(yy, xx);
            if (phi < 0.0f) phi += TWO_PI_F;

            float v[7];
            v[0] = fmaxf(0.0f, 1.0f - r * (1.0f / DR_F)) * mask;
            #pragma unroll
            for (int k = 1; k < 7; ++k) {
                int ir = (k - 1) / 3 + 1;
                int ip = (k - 1) % 3;
                float rad = fmaxf(0.0f, 1.0f - fabsf(r - (float)ir * DR_F) * (1.0f / DR_F));
                float dd  = fabsf(phi - (float)ip * DPH_F);
                dd = fminf(dd, TWO_PI_F - dd);
                float az = fmaxf(0.0f, 1.0f - dd * (1.0f / DPH_F));
                v[k] = rad * az * mask;
            }
            size_t b8 = ((size_t)(t * 21 + d) * 728 + s) * 8;
            g_psi8[b8 + 0] = v[1];
            g_psi8[b8 + 1] = v[2];
            g_psi8[b8 + 2] = v[3];
            g_psi8[b8 + 3] = v[6];
            g_psi8[b8 + 4] = v[4];
            g_psi8[b8 + 5] = v[5];
            g_psi8[b8 + 6] = v[0];
            g_psi8[b8 + 7] = 0.0f;
            #pragma unroll
            for (int k = 0; k < 7; ++k) sums[k] += v[k];
        }
    }

    __shared__ float red[8][7];
    int lane = tid & 31, w = tid >> 5;
    #pragma unroll
    for (int k = 0; k < 7; ++k) {
        float s = sums[k];
        #pragma unroll
        for (int o = 16; o > 0; o >>= 1) s += __shfl_down_sync(0xffffffffu, s, o);
        if (lane == 0) red[w][k] = s;
    }
    __syncthreads();
    if (tid < 7) {
        float s = 0.0f;
        #pragma unroll
        for (int ww = 0; ww < 8; ++ww) s += red[ww][tid];
        g_sp[(tid * 361 + t) * 21 + d] = s;
    }
}

// ---------------- kernel INV+PACK (merged -> 4-kernel pattern) ----------------
__global__ void invpack_kernel(const float* __restrict__ wgt) {
    int idx = blockIdx.x * 256 + threadIdx.x;
    if (idx < 32 * 112) {
        int o = idx / 112;
        int j = idx - o * 112;
        int k = j >> 4;
        int h = j & 15;
        g_w2[idx * 2 + 0] = wgt[(o * CI + 2 * h) * KK + k];
        g_w2[idx * 2 + 1] = wgt[(o * CI + 2 * h + 1) * KK + k];
    }
    if (idx < 361) {
        float inv[7];
        #pragma unroll
        for (int k = 0; k < 7; ++k) {
            float s = 0.0f;
            #pragma unroll
            for (int d = 0; d < 21; ++d) s += g_sp[(k * 361 + idx) * 21 + d];
            inv[k] = 1.0f / fmaxf(s, 1e-8f);
        }
        // slot order: k1,k2,k3,k6,k4,k5,k0
        g_invs2[idx * 8 + 0] = inv[1];
        g_invs2[idx * 8 + 1] = inv[2];
        g_invs2[idx * 8 + 2] = inv[3];
        g_invs2[idx * 8 + 3] = inv[6];
        g_invs2[idx * 8 + 4] = inv[4];
        g_invs2[idx * 8 + 5] = inv[5];
        g_invs2[idx * 8 + 6] = inv[0];
        g_invs2[idx * 8 + 7] = 0.0f;
    }
}

// ---------------- kernel C: conv + fused GEMM ----------------
// phase1 smem: xu float4[8][720] (92160B) + psi float[728][8] (23296B) = 115456B
// phase2 (aliased): z2 float[112][64][2] = 57344B
#define SMEM_C (8 * 720 * 16 + 728 * 8 * 4)

#define PDUP(dst, v)     asm("mov.b64 %0,{%1,%1};" : "=l"(dst) : "f"(v))
#define UNP(lo, hi, v)   asm("mov.b64 {%0,%1},%2;" : "=f"(lo), "=f"(hi) : "l"(v))
#define F2(acc, p, x)    asm("fma.rn.f32x2 %0,%1,%2,%0;" : "+l"(acc) : "l"(p), "l"(x))
#define M2(acc, s)       asm("mul.rn.f32x2 %0,%0,%1;" : "+l"(acc) : "l"(s))

#define FMA_S(SL, P)                                                     \
    F2(aK[SL][0], P, v0.x); F2(aK[SL][1], P, v0.y);                      \
    F2(aK[SL][2], P, v1.x); F2(aK[SL][3], P, v1.y);

// OUT (r>2dr): k4,k5 (v2 @+16) + k6 (scalar @+12) -> slots 4,5,3
#define BODY_OUT(Q, SS) {                                                \
    ulonglong2 v0 = xs0[Q];                                              \
    ulonglong2 v1 = xs1[Q];                                              \
    float k4s, k5s, k6s;                                                 \
    asm("ld.shared.v2.f32 {%0,%1},[%2];" : "=f"(k4s), "=f"(k5s)          \
        : "r"(psi_u + (unsigned)(SS) * 32u + 16u));                      \
    asm("ld.shared.f32 %0,[%1];" : "=f"(k6s)                             \
        : "r"(psi_u + (unsigned)(SS) * 32u + 12u));                      \
    u64 p4, p5, p6;                                                      \
    PDUP(p4, k4s); PDUP(p5, k5s); PDUP(p6, k6s);                         \
    FMA_S(4, p4) FMA_S(5, p5) FMA_S(3, p6) }

// MID6 (dr<r<2dr): k1,k2,k3,k6 (v4 @0) + k4,k5 (v2 @+16) -> slots 0..5
#define BODY_MID6(Q, SS) {                                               \
    ulonglong2 v0 = xs0[Q];                                              \
    ulonglong2 v1 = xs1[Q];                                              \
    float s0, s1, s2, s3, k4s, k5s;                                      \
    asm("ld.shared.v4.f32 {%0,%1,%2,%3},[%4];"                           \
        : "=f"(s0), "=f"(s1), "=f"(s2), "=f"(s3)                         \
        : "r"(psi_u + (unsigned)(SS) * 32u));                            \
    asm("ld.shared.v2.f32 {%0,%1},[%2];" : "=f"(k4s), "=f"(k5s)          \
        : "r"(psi_u + (unsigned)(SS) * 32u + 16u));                      \
    u64 p0, p1, p2, p3, p4, p5;                                          \
    PDUP(p0, s0); PDUP(p1, s1); PDUP(p2, s2); PDUP(p3, s3);              \
    PDUP(p4, k4s); PDUP(p5, k5s);                                        \
    FMA_S(0, p0) FMA_S(1, p1) FMA_S(2, p2) FMA_S(3, p3)                  \
    FMA_S(4, p4) FMA_S(5, p5) }

// MID7 transition: all 7 (adds k0 scalar @+24 -> slot 6)
#define BODY_MID7(Q, SS) {                                               \
    ulonglong2 v0 = xs0[Q];                                              \
    ulonglong2 v1 = xs1[Q];                                              \
    float s0, s1, s2, s3, k4s, k5s, k0s;                                 \
    asm("ld.shared.v4.f32 {%0,%1,%2,%3},[%4];"                           \
        : "=f"(s0), "=f"(s1), "=f"(s2), "=f"(s3)                         \
        : "r"(psi_u + (unsigned)(SS) * 32u));                            \
    asm("ld.shared.v2.f32 {%0,%1},[%2];" : "=f"(k4s), "=f"(k5s)          \
        : "r"(psi_u + (unsigned)(SS) * 32u + 16u));                      \
    asm("ld.shared.f32 %0,[%1];" : "=f"(k0s)                             \
        : "r"(psi_u + (unsigned)(SS) * 32u + 24u));                      \
    u64 p0, p1, p2, p3, p4, p5, p6;                                      \
    PDUP(p0, s0); PDUP(p1, s1); PDUP(p2, s2); PDUP(p3, s3);              \
    PDUP(p4, k4s); PDUP(p5, k5s); PDUP(p6, k0s);                         \
    FMA_S(0, p0) FMA_S(1, p1) FMA_S(2, p2) FMA_S(3, p3)                  \
    FMA_S(4, p4) FMA_S(5, p5) FMA_S(6, p6) }

// IN4 (r<dr): k1,k2 (v2 @0) + k3 (scalar @+8) + k0 (scalar @+24) -> slots 0,1,2,6
#define BODY_IN4(Q, SS) {                                                \
    ulonglong2 v0 = xs0[Q];                                              \
    ulonglong2 v1 = xs1[Q];                                              \
    float s0, s1, s2, k0s;                                               \
    asm("ld.shared.v2.f32 {%0,%1},[%2];" : "=f"(s0), "=f"(s1)            \
        : "r"(psi_u + (unsigned)(SS) * 32u));                            \
    asm("ld.shared.f32 %0,[%1];" : "=f"(s2)                              \
        : "r"(psi_u + (unsigned)(SS) * 32u + 8u));                       \
    asm("ld.shared.f32 %0,[%1];" : "=f"(k0s)                             \
        : "r"(psi_u + (unsigned)(SS) * 32u + 24u));                      \
    u64 p0, p1, p2, p6;                                                  \
    PDUP(p0, s0); PDUP(p1, s1); PDUP(p2, s2); PDUP(p6, k0s);             \
    FMA_S(0, p0) FMA_S(1, p1) FMA_S(2, p2) FMA_S(6, p6) }

#define BAND2_LIN(BODY, END)                                             \
    for (; s + 1 < (END); s += 2) { BODY(s, s) BODY(s + 1, s + 1) }      \
    if (s < (END)) { BODY(s, s) ++s; }

#define BAND2_WRAP(BODY, END)                                            \
    for (; s + 1 < (END); s += 2) {                                      \
        int q1 = q + 1; if (q1 >= 720) q1 -= 720;                        \
        BODY(q, s) BODY(q1, s + 1)                                       \
        q = q1 + 1; if (q >= 720) q -= 720;                              \
    }                                                                    \
    if (s < (END)) { BODY(q, s) ++s; ++q; if (q >= 720) q -= 720; }

__global__ void __launch_bounds__(256, 2)
conv_kernel(float* __restrict__ y) {
    extern __shared__ float sm[];
    float4* xu_s  = (float4*)sm;                        // [8][720]
    float*  psi_s = sm + 8 * 720 * 4;                   // [728][8]
    unsigned psi_u = (unsigned)__cvta_generic_to_shared(psi_s);

    int ty = blockIdx.y;
    int t  = (ty & 1) ? (360 - (ty >> 1)) : (ty >> 1);  // heavy rows first
    int p0 = blockIdx.x * 64;
    int tid  = threadIdx.x;
    int lane = tid & 31;
    int wpi  = tid >> 5;
    int sub  = wpi & 1;                                 // p-subtile
    int cg   = wpi >> 1;                                // channel octet
    int qb   = 32 * sub + lane;

    u64 aK[7][4];
    #pragma unroll
    for (int k = 0; k < 7; ++k)
        #pragma unroll
        for (int j = 0; j < 4; ++j) aK[k][j] = 0ull;

    const float4* gx = (const float4*)g_xu4;

    for (int d = 0; d < 21; ++d) {
        int lt = t + d - WOFF;
        if (lt < 0 || lt > 360) continue;
        int m = g_m[t * 21 + d];
        if (m < 0) continue;
        int m2  = g_m2[t * 21 + d];
        int m1s = g_m1[t * 21 + d];
        int m1g = g_m1g[t * 21 + d];
        int cnt = 2 * m + 1;
        int L = 64 + 2 * m;
        int n = (L < 720) ? L : 720;
        int base = p0 - m;
        base %= 720; if (base < 0) base += 720;

        int oL, oR, gL, gR, sL, sR;
        if (m2 < 0)  { oL = cnt; oR = cnt; }
        else         { oL = max(0, m - m2); oR = min(cnt, m + m2 + 1); }
        if (m1g < 0) { gL = oR; gR = oR; }
        else         { gL = max(oL, m - m1g); gR = min(oR, m + m1g + 1); }
        if (m1s < 0) { sL = gR; sR = gR; }
        else         { sL = max(gL, m - m1s); sR = min(gR, m + m1s + 1); }

        __syncthreads();
        // stage xu window: warp wpi stages group wpi
        {
            const float4* src = gx + ((size_t)wpi * NLAT_O + lt) * NLON_O;
            for (int q = lane; q < n; q += 32) {
                int lon = base + q; if (lon >= 720) lon -= 720;
                xu_s[wpi * 720 + q] = src[lon];
            }
        }
        // stage psi (pure copy, 32B per s-entry)
        {
            const float4* src = (const float4*)(g_psi8 + ((size_t)(t * 21 + d)) * 728 * 8);
            float4* dst = (float4*)psi_s;
            for (int s2 = tid; s2 < 2 * cnt; s2 += 256) dst[s2] = src[s2];
        }
        __syncthreads();

        int s = 0;
        if (n < 720) {
            const ulonglong2* xs0 = (const ulonglong2*)(xu_s + (2 * cg) * 720) + qb;
            const ulonglong2* xs1 = xs0 + 720;
            BAND2_LIN(BODY_OUT,  oL)
            BAND2_LIN(BODY_MID6, gL)
            BAND2_LIN(BODY_MID7, sL)
            BAND2_LIN(BODY_IN4,  sR)
            BAND2_LIN(BODY_MID7, gR)
            BAND2_LIN(BODY_MID6, oR)
            BAND2_LIN(BODY_OUT,  cnt)
        } else {
            const ulonglong2* xs0 = (const ulonglong2*)(xu_s + (2 * cg) * 720);
            const ulonglong2* xs1 = xs0 + 720;
            int q = qb;
            BAND2_WRAP(BODY_OUT,  oL)
            BAND2_WRAP(BODY_MID6, gL)
            BAND2_WRAP(BODY_MID7, sL)
            BAND2_WRAP(BODY_IN4,  sR)
            BAND2_WRAP(BODY_MID7, gR)
            BAND2_WRAP(BODY_MID6, oR)
            BAND2_WRAP(BODY_OUT,  cnt)
        }
    }

    // ---- fold 1/scale (slot order matches aK) ----
    {
        const float* iv = g_invs2 + t * 8;
        #pragma unroll
        for (int k = 0; k < 7; ++k) {
            u64 dk;
            PDUP(dk, iv[k]);
            #pragma unroll
            for (int j = 0; j < 4; ++j) M2(aK[k][j], dk);
        }
    }

    __syncthreads();
    // ---- phase 2: scatter z [112 kpair][64 p][2 par], GEMM ----
    u64* z2w = (u64*)sm;
    {
        const int kmap[7] = {1, 2, 3, 6, 4, 5, 0};
        #pragma unroll
        for (int sl = 0; sl < 7; ++sl)
            #pragma unroll
            for (int j = 0; j < 4; ++j)
                z2w[(kmap[sl] * 16 + 4 * cg + j) * 64 + qb] = aK[sl][j];
    }
    __syncthreads();

    // GEMM: thread = 2 adjacent p x 4 o
    int po2 = tid & 31;
    int og  = (tid >> 5) & 7;
    const ulonglong2* zp = (const ulonglong2*)z2w;
    const u64* wu = (const u64*)g_w2;

    u64 acc0[4], acc1[4];
    #pragma unroll
    for (int oo = 0; oo < 4; ++oo) { acc0[oo] = 0ull; acc1[oo] = 0ull; }

    for (int j = 0; j < 112; ++j) {
        ulonglong2 zv = zp[j * 32 + po2];
        #pragma unroll
        for (int oo = 0; oo < 4; ++oo) {
            u64 wv = __ldg(wu + (og + 8 * oo) * 112 + j);
            F2(acc0[oo], wv, zv.x);
            F2(acc1[oo], wv, zv.y);
        }
    }

    int pA0 = p0 + 2 * po2;
    int pA1 = pA0 + 1;
    #pragma unroll
    for (int oo = 0; oo < 4; ++oo) {
        int o = og + 8 * oo;
        float lo, hi;
        if (pA0 < 720) {
            UNP(lo, hi, acc0[oo]);
            y[((size_t)o * NLAT_O + t) * NLON_O + pA0] = lo + hi;
        }
        if (pA1 < 720) {
            UNP(lo, hi, acc1[oo]);
            y[((size_t)o * NLAT_O + t) * NLON_O + pA1] = lo + hi;
        }
    }
}

// ---------------- launcher (4 kernels -> conv lands in the ncu -s 5 slot) ----------------
extern "C" void kernel_launch(void* const* d_in, const int* in_sizes, int n_in,
                              void* d_out, int out_size) {
    const float* x = (const float*)d_in[0];       // [1,32,240,480]
    const float* w = (const float*)d_in[1];       // [32,32,7]
    float* y = (float*)d_out;                     // [1,32,361,720]

    cudaFuncSetAttribute(conv_kernel, cudaFuncAttributeMaxDynamicSharedMemorySize, SMEM_C);

    int nA = CI * NLAT_O * NLON_O;
    upsample_kernel<<<(nA + 255) / 256, 256>>>(x);
    build_psi_kernel<<<dim3(21, 361), 256>>>();
    invpack_kernel<<<(32 * 112 + 255) / 256, 256>>>(w);
    conv_kernel<<<dim3(12, 361), 256, SMEM_C>>>(y);
}